// round 6
// baseline (speedup 1.0000x reference)
#include <cuda_runtime.h>
#include <math.h>

#define NN 50000
#define EE 800000
#define HH 8

// ---------------- scratch (device globals: no allocation allowed) -------------
__device__ float g_xw[NN * 256];          // [x@W0 | x@W1], row stride 256 (1KB rows)
__device__ float g_as[2][NN * HH];        // per-node, per-head att_src logits (hop 0/1)
__device__ float g_ad[2][NN * HH];        // per-node, per-head att_dst logits
__device__ int   g_cnt[2][NN];            // counts, then cursors
__device__ int   g_off[2][NN + 1];        // CSR offsets (by dst)
__device__ int   g_csr[2][EE];            // src node per in-edge
__device__ int   g_is64;                  // 1 if edge_index is int64, 0 if int32

// ---------------------------------- utils ------------------------------------
__device__ __forceinline__ float lrelu(float v) { return v >= 0.f ? v : 0.2f * v; }

// Read edge_index element idx (idx in [0, 2*EE)) regardless of storage dtype.
__device__ __forceinline__ int edge_val(const void* ei, int idx, int is64) {
    if (is64) return (int)((const long long*)ei)[idx];
    return ((const int*)ei)[idx];
}

// dtype probe + counter zeroing fused.
// int64 node ids < 50000 have zero high words at odd int32 slots; int32 data
// has real random ids there (all-zero probability ~0).
__global__ void init_kernel(const int* __restrict__ p) {
    int i = blockIdx.x * blockDim.x + threadIdx.x;
    if (i < NN) { g_cnt[0][i] = 0; g_cnt[1][i] = 0; }
    if (blockIdx.x == 0) {
        __shared__ int any_nonzero;
        if (threadIdx.x == 0) any_nonzero = 0;
        __syncthreads();
        int v = 0;
        for (int j = threadIdx.x; j < 2048; j += blockDim.x) v |= p[2 * j + 1];
        if (v) atomicOr(&any_nonzero, 1);
        __syncthreads();
        if (threadIdx.x == 0) g_is64 = (any_nonzero == 0) ? 1 : 0;
    }
}

// ------------------------------ SGEMM: xw = x @ [W0|W1] -----------------------
// BM=128, BN=128, BK=8, 256 threads, 8x8 per-thread tile. blockIdx.y selects W0/W1.
__global__ void __launch_bounds__(256) gemm_kernel(const float* __restrict__ A,
                                                   const float* __restrict__ W0,
                                                   const float* __restrict__ W1) {
    const float* B = blockIdx.y ? W1 : W0;   // [256][128]
    const int block_row = blockIdx.x * 128;

    __shared__ float As[8][128];
    __shared__ float Bs[8][128];

    float acc[8][8];
#pragma unroll
    for (int i = 0; i < 8; i++)
#pragma unroll
        for (int j = 0; j < 8; j++) acc[i][j] = 0.f;

    const int tid = threadIdx.x;
    const int tx = tid & 15, ty = tid >> 4;
    const int a_row = tid >> 1;
    const int a_col4 = (tid & 1) * 4;
    const int b_row = tid >> 5;
    const int b_col = (tid & 31) * 4;

    for (int k0 = 0; k0 < 256; k0 += 8) {
        int gr = block_row + a_row;
        float4 av = make_float4(0.f, 0.f, 0.f, 0.f);
        if (gr < NN) av = *(const float4*)(A + gr * 256 + k0 + a_col4);
        As[a_col4 + 0][a_row] = av.x;
        As[a_col4 + 1][a_row] = av.y;
        As[a_col4 + 2][a_row] = av.z;
        As[a_col4 + 3][a_row] = av.w;
        float4 bv = *(const float4*)(B + (k0 + b_row) * 128 + b_col);
        *(float4*)&Bs[b_row][b_col] = bv;
        __syncthreads();
#pragma unroll
        for (int kk = 0; kk < 8; kk++) {
            float ar[8], br[8];
            *(float4*)&ar[0] = *(const float4*)&As[kk][ty * 8];
            *(float4*)&ar[4] = *(const float4*)&As[kk][ty * 8 + 4];
            *(float4*)&br[0] = *(const float4*)&Bs[kk][tx * 8];
            *(float4*)&br[4] = *(const float4*)&Bs[kk][tx * 8 + 4];
#pragma unroll
            for (int i = 0; i < 8; i++)
#pragma unroll
                for (int j = 0; j < 8; j++) acc[i][j] += ar[i] * br[j];
        }
        __syncthreads();
    }

    const int colbase = blockIdx.y * 128 + tx * 8;
#pragma unroll
    for (int i = 0; i < 8; i++) {
        int r = block_row + ty * 8 + i;
        if (r < NN) {
            *(float4*)(g_xw + r * 256 + colbase)     = make_float4(acc[i][0], acc[i][1], acc[i][2], acc[i][3]);
            *(float4*)(g_xw + r * 256 + colbase + 4) = make_float4(acc[i][4], acc[i][5], acc[i][6], acc[i][7]);
        }
    }
}

// -------------------- per-node attention dot products -------------------------
// Thread per (node, hop, head): 16 consecutive threads cover one node's 256 floats.
__global__ void att_kernel(const float* __restrict__ as0, const float* __restrict__ ad0,
                           const float* __restrict__ as1, const float* __restrict__ ad1) {
    int t = blockIdx.x * blockDim.x + threadIdx.x;   // t in [0, NN*16)
    if (t >= NN * 16) return;
    int h  = t & 7;
    int hp = (t >> 3) & 1;
    int n  = t >> 4;
    const float* xr = g_xw + n * 256 + hp * 128 + h * 16;
    const float* ap = (hp ? as1 : as0) + h * 16;
    const float* dp = (hp ? ad1 : ad0) + h * 16;
    float ps = 0.f, pd = 0.f;
#pragma unroll
    for (int c = 0; c < 16; c++) {
        float v = xr[c];
        ps += v * __ldg(ap + c);
        pd += v * __ldg(dp + c);
    }
    g_as[hp][n * HH + h] = ps;
    g_ad[hp][n * HH + h] = pd;
}

// ------------------------------ CSR build -------------------------------------
__global__ void count_kernel(const void* __restrict__ ei) {
    int e = blockIdx.x * blockDim.x + threadIdx.x;
    if (e >= EE) return;
    const int is64 = g_is64;
    int d1 = edge_val(ei, EE + e, is64);
    if (d1 < 0 || d1 >= NN) return;          // safety guard
    atomicAdd(&g_cnt[0][d1], 1);
    int d2 = edge_val(ei, EE + d1, is64);    // hop-2 dst: col[col[e]]
    if (d2 < 0 || d2 >= NN) return;
    atomicAdd(&g_cnt[1][d2], 1);
}

// exclusive scan per hop (block b scans hop b); zeroes cnt for reuse as cursor
__global__ void scan_kernel() {
    __shared__ int tmp[1024];
    __shared__ int carry;
    int hop = blockIdx.x;
    int tid = threadIdx.x;
    if (tid == 0) carry = 0;
    __syncthreads();
    for (int base = 0; base < NN; base += 1024) {
        int i = base + tid;
        int v = (i < NN) ? g_cnt[hop][i] : 0;
        if (i < NN) g_cnt[hop][i] = 0;
        tmp[tid] = v;
        __syncthreads();
        for (int d = 1; d < 1024; d <<= 1) {
            int t = (tid >= d) ? tmp[tid - d] : 0;
            __syncthreads();
            tmp[tid] += t;
            __syncthreads();
        }
        int c = carry;
        if (i < NN) g_off[hop][i] = c + tmp[tid] - v;
        __syncthreads();
        if (tid == 0) carry = c + tmp[1023];
        __syncthreads();
    }
    if (tid == 0) g_off[hop][NN] = carry;
}

__global__ void fill_kernel(const void* __restrict__ ei) {
    int e = blockIdx.x * blockDim.x + threadIdx.x;
    if (e >= EE) return;
    const int is64 = g_is64;
    int s1 = edge_val(ei, e, is64);
    int d1 = edge_val(ei, EE + e, is64);
    if (s1 < 0 || s1 >= NN || d1 < 0 || d1 >= NN) return;  // safety guard
    int p = atomicAdd(&g_cnt[0][d1], 1);
    g_csr[0][g_off[0][d1] + p] = s1;
    int s2 = edge_val(ei, d1, is64);
    int d2 = edge_val(ei, EE + d1, is64);
    if (s2 < 0 || s2 >= NN || d2 < 0 || d2 >= NN) return;
    int p2 = atomicAdd(&g_cnt[1][d2], 1);
    g_csr[1][g_off[1][d2] + p2] = s2;
}

// -------------------- GAT aggregation: warp per dst node ----------------------
// Single pass, no max subtraction (shift cancels exactly in alpha; logits O(1)).
// KEY SEMANTIC: hop 2's edge list contains each node's self-loop TWICE
// (once from _get_next_hop_edges, once from _gat_conv's add_self_loops), so the
// self-loop term enters numerator and denominator with weight 2 for hop==1.
__global__ void aggregate_kernel(const float* __restrict__ bias, float* __restrict__ out, int hop) {
    int w = (blockIdx.x * blockDim.x + threadIdx.x) >> 5;
    int l = threadIdx.x & 31;
    if (w >= NN) return;
    const int*   __restrict__ csr = g_csr[hop];
    const float* __restrict__ AS  = g_as[hop];
    const float* __restrict__ AD  = g_ad[hop];
    const int n = w;
    const int beg = g_off[hop][n], end = g_off[hop][n + 1];
    const int head = l >> 2;
    const float self_mult = (hop == 1) ? 2.0f : 1.0f;

    float ad_l = 0.f, as_n = 0.f;
    if (l < HH) { ad_l = AD[n * HH + l]; as_n = AS[n * HH + l]; }
    // self-loop weight (lanes 0..7, one per head); duplicated self-loop for hop 2
    float sh = (l < HH) ? self_mult * expf(lrelu(as_n + ad_l)) : 0.f;

    float pb = __shfl_sync(0xffffffffu, sh, head);
    float4 xv = *(const float4*)(g_xw + n * 256 + hop * 128 + l * 4);
    float4 acc = make_float4(pb * xv.x, pb * xv.y, pb * xv.z, pb * xv.w);

    for (int base = beg; base < end; base += 32) {
        int src = 0;
        if (base + l < end) src = csr[base + l];
        int cnt = min(32, end - base);
        for (int k = 0; k < cnt; k++) {
            int s = __shfl_sync(0xffffffffu, src, k);
            float p = 0.f;
            if (l < HH) {
                p = expf(lrelu(AS[s * HH + l] + ad_l));
                sh += p;
            }
            float pw = __shfl_sync(0xffffffffu, p, head);
            float4 mv = __ldg((const float4*)(g_xw + s * 256 + hop * 128 + l * 4));
            acc.x += pw * mv.x;
            acc.y += pw * mv.y;
            acc.z += pw * mv.z;
            acc.w += pw * mv.w;
        }
    }

    float st = __shfl_sync(0xffffffffu, sh, head);
    float inv = 1.0f / st;
    float4 bv = *(const float4*)(bias + l * 4);
    float4 o = make_float4(acc.x * inv + bv.x, acc.y * inv + bv.y,
                           acc.z * inv + bv.z, acc.w * inv + bv.w);
    *(float4*)(out + n * 256 + hop * 128 + l * 4) = o;
}

// ---------------------- residual + LayerNorm (in-place) -----------------------
__global__ void ln_kernel(const float* __restrict__ x, const float* __restrict__ gamma,
                          const float* __restrict__ beta, float* __restrict__ out) {
    int w = (blockIdx.x * blockDim.x + threadIdx.x) >> 5;
    int l = threadIdx.x & 31;
    if (w >= NN) return;
    const int base = w * 256 + l * 8;
    float4 h0 = *(float4*)(out + base);
    float4 h1 = *(float4*)(out + base + 4);
    float4 x0 = *(const float4*)(x + base);
    float4 x1 = *(const float4*)(x + base + 4);
    float v[8] = {h0.x + x0.x, h0.y + x0.y, h0.z + x0.z, h0.w + x0.w,
                  h1.x + x1.x, h1.y + x1.y, h1.z + x1.z, h1.w + x1.w};
    float s = 0.f;
#pragma unroll
    for (int j = 0; j < 8; j++) s += v[j];
#pragma unroll
    for (int d = 16; d; d >>= 1) s += __shfl_xor_sync(0xffffffffu, s, d);
    float mean = s * (1.0f / 256.0f);
    float q = 0.f;
#pragma unroll
    for (int j = 0; j < 8; j++) { float t = v[j] - mean; q += t * t; }
#pragma unroll
    for (int d = 16; d; d >>= 1) q += __shfl_xor_sync(0xffffffffu, q, d);
    float rstd = rsqrtf(q * (1.0f / 256.0f) + 1e-5f);
    float4 g0 = *(const float4*)(gamma + l * 8);
    float4 g1 = *(const float4*)(gamma + l * 8 + 4);
    float4 b0 = *(const float4*)(beta + l * 8);
    float4 b1 = *(const float4*)(beta + l * 8 + 4);
    float4 o0 = make_float4((v[0] - mean) * rstd * g0.x + b0.x,
                            (v[1] - mean) * rstd * g0.y + b0.y,
                            (v[2] - mean) * rstd * g0.z + b0.z,
                            (v[3] - mean) * rstd * g0.w + b0.w);
    float4 o1 = make_float4((v[4] - mean) * rstd * g1.x + b1.x,
                            (v[5] - mean) * rstd * g1.y + b1.y,
                            (v[6] - mean) * rstd * g1.z + b1.z,
                            (v[7] - mean) * rstd * g1.w + b1.w);
    *(float4*)(out + base)     = o0;
    *(float4*)(out + base + 4) = o1;
}

// ------------------------------- launcher -------------------------------------
extern "C" void kernel_launch(void* const* d_in, const int* in_sizes, int n_in,
                              void* d_out, int out_size) {
    const float* x     = (const float*)d_in[0];
    const void*  ei    = d_in[1];
    const float* W0    = (const float*)d_in[2];
    const float* as0   = (const float*)d_in[3];
    const float* ad0   = (const float*)d_in[4];
    const float* b0    = (const float*)d_in[5];
    const float* W1    = (const float*)d_in[6];
    const float* as1   = (const float*)d_in[7];
    const float* ad1   = (const float*)d_in[8];
    const float* b1    = (const float*)d_in[9];
    const float* gamma = (const float*)d_in[10];
    const float* beta  = (const float*)d_in[11];
    float* out = (float*)d_out;

    init_kernel<<<(NN + 255) / 256, 256>>>((const int*)ei);
    gemm_kernel<<<dim3((NN + 127) / 128, 2), 256>>>(x, W0, W1);
    att_kernel<<<(NN * 16 + 255) / 256, 256>>>(as0, ad0, as1, ad1);
    count_kernel<<<(EE + 255) / 256, 256>>>(ei);
    scan_kernel<<<2, 1024>>>();
    fill_kernel<<<(EE + 255) / 256, 256>>>(ei);
    aggregate_kernel<<<(NN * 32 + 255) / 256, 256>>>(b0, out, 0);
    aggregate_kernel<<<(NN * 32 + 255) / 256, 256>>>(b1, out, 1);
    ln_kernel<<<(NN * 32 + 255) / 256, 256>>>(x, gamma, beta, out);
}

// round 7
// speedup vs baseline: 1.0165x; 1.0165x over previous
#include <cuda_runtime.h>
#include <math.h>

#define NN 50000
#define EE 800000
#define HH 8

// ---------------- scratch (device globals: no allocation allowed) -------------
__device__ float g_xw[NN * 256];          // [x@W0 | x@W1], row stride 256 (1KB rows)
__device__ float g_as[2][NN * HH];        // per-node, per-head att_src logits (hop 0/1)
__device__ float g_ad[2][NN * HH];        // per-node, per-head att_dst logits
__device__ int   g_cnt[2][NN];            // counts, then cursors
__device__ int   g_off[2][NN + 1];        // CSR offsets (by dst)
__device__ int   g_csr[2][EE];            // src node per in-edge
__device__ int   g_is64;                  // 1 if edge_index is int64, 0 if int32

// ---------------------------------- utils ------------------------------------
__device__ __forceinline__ float lrelu(float v) { return v >= 0.f ? v : 0.2f * v; }

__device__ __forceinline__ int edge_val(const void* ei, int idx, int is64) {
    if (is64) return (int)((const long long*)ei)[idx];
    return ((const int*)ei)[idx];
}

// packed fp32x2 FMA: c = a*b + c elementwise on 2-lane packed fp32 (exact fp32)
__device__ __forceinline__ void ffma2(unsigned long long& c, unsigned long long a,
                                      unsigned long long b) {
    asm("fma.rn.f32x2 %0, %1, %2, %0;" : "+l"(c) : "l"(a), "l"(b));
}
__device__ __forceinline__ unsigned long long pack_dup(float a) {
    unsigned long long r;
    asm("mov.b64 %0, {%1, %1};" : "=l"(r) : "f"(a));
    return r;
}

// dtype probe + counter zeroing fused.
__global__ void init_kernel(const int* __restrict__ p) {
    int i = blockIdx.x * blockDim.x + threadIdx.x;
    if (i < NN) { g_cnt[0][i] = 0; g_cnt[1][i] = 0; }
    if (blockIdx.x == 0) {
        __shared__ int any_nonzero;
        if (threadIdx.x == 0) any_nonzero = 0;
        __syncthreads();
        int v = 0;
        for (int j = threadIdx.x; j < 2048; j += blockDim.x) v |= p[2 * j + 1];
        if (v) atomicOr(&any_nonzero, 1);
        __syncthreads();
        if (threadIdx.x == 0) g_is64 = (any_nonzero == 0) ? 1 : 0;
    }
}

// ------------------------------ SGEMM: xw = x @ [W0|W1] -----------------------
// BM=128, BN=128, BK=8, 256 threads, 8x8 per-thread tile, FFMA2 (f32x2) inner.
// Accumulators are 4 packed f32x2 per row-slot (= 8 columns).
__global__ void __launch_bounds__(256) gemm_kernel(const float* __restrict__ A,
                                                   const float* __restrict__ W0,
                                                   const float* __restrict__ W1) {
    const float* B = blockIdx.y ? W1 : W0;   // [256][128]
    const int block_row = blockIdx.x * 128;

    __shared__ float As[8][128];
    __shared__ float Bs[8][128];

    unsigned long long acc2[8][4];           // [i][j-pair], (0.f,0.f) == 0ull
#pragma unroll
    for (int i = 0; i < 8; i++)
#pragma unroll
        for (int j = 0; j < 4; j++) acc2[i][j] = 0ull;

    const int tid = threadIdx.x;
    const int tx = tid & 15, ty = tid >> 4;
    const int a_row = tid >> 1;
    const int a_col4 = (tid & 1) * 4;
    const int b_row = tid >> 5;
    const int b_col = (tid & 31) * 4;

    for (int k0 = 0; k0 < 256; k0 += 8) {
        int gr = block_row + a_row;
        float4 av = make_float4(0.f, 0.f, 0.f, 0.f);
        if (gr < NN) av = *(const float4*)(A + gr * 256 + k0 + a_col4);
        As[a_col4 + 0][a_row] = av.x;
        As[a_col4 + 1][a_row] = av.y;
        As[a_col4 + 2][a_row] = av.z;
        As[a_col4 + 3][a_row] = av.w;
        float4 bv = *(const float4*)(B + (k0 + b_row) * 128 + b_col);
        *(float4*)&Bs[b_row][b_col] = bv;
        __syncthreads();
#pragma unroll
        for (int kk = 0; kk < 8; kk++) {
            float ar[8];
            *(float4*)&ar[0] = *(const float4*)&As[kk][ty * 8];
            *(float4*)&ar[4] = *(const float4*)&As[kk][ty * 8 + 4];
            unsigned long long br2[4];
            {   // 8 consecutive floats = 4 packed f32x2 (16B-aligned in smem)
                ulonglong2 b01 = *(const ulonglong2*)&Bs[kk][tx * 8];
                ulonglong2 b23 = *(const ulonglong2*)&Bs[kk][tx * 8 + 4];
                br2[0] = b01.x; br2[1] = b01.y; br2[2] = b23.x; br2[3] = b23.y;
            }
#pragma unroll
            for (int i = 0; i < 8; i++) {
                unsigned long long aa = pack_dup(ar[i]);
                ffma2(acc2[i][0], aa, br2[0]);
                ffma2(acc2[i][1], aa, br2[1]);
                ffma2(acc2[i][2], aa, br2[2]);
                ffma2(acc2[i][3], aa, br2[3]);
            }
        }
        __syncthreads();
    }

    const int colbase = blockIdx.y * 128 + tx * 8;
#pragma unroll
    for (int i = 0; i < 8; i++) {
        int r = block_row + ty * 8 + i;
        if (r < NN) {
            *(ulonglong2*)(g_xw + r * 256 + colbase)     = make_ulonglong2(acc2[i][0], acc2[i][1]);
            *(ulonglong2*)(g_xw + r * 256 + colbase + 4) = make_ulonglong2(acc2[i][2], acc2[i][3]);
        }
    }
}

// -------------------- per-node attention dot products -------------------------
__global__ void att_kernel(const float* __restrict__ as0, const float* __restrict__ ad0,
                           const float* __restrict__ as1, const float* __restrict__ ad1) {
    int t = blockIdx.x * blockDim.x + threadIdx.x;   // t in [0, NN*16)
    if (t >= NN * 16) return;
    int h  = t & 7;
    int hp = (t >> 3) & 1;
    int n  = t >> 4;
    const float* xr = g_xw + n * 256 + hp * 128 + h * 16;
    const float* ap = (hp ? as1 : as0) + h * 16;
    const float* dp = (hp ? ad1 : ad0) + h * 16;
    float ps = 0.f, pd = 0.f;
#pragma unroll
    for (int c = 0; c < 16; c++) {
        float v = xr[c];
        ps += v * __ldg(ap + c);
        pd += v * __ldg(dp + c);
    }
    g_as[hp][n * HH + h] = ps;
    g_ad[hp][n * HH + h] = pd;
}

// ------------------------------ CSR build -------------------------------------
__global__ void count_kernel(const void* __restrict__ ei) {
    int e = blockIdx.x * blockDim.x + threadIdx.x;
    if (e >= EE) return;
    const int is64 = g_is64;
    int d1 = edge_val(ei, EE + e, is64);
    if (d1 < 0 || d1 >= NN) return;
    atomicAdd(&g_cnt[0][d1], 1);
    int d2 = edge_val(ei, EE + d1, is64);    // hop-2 dst: col[col[e]]
    if (d2 < 0 || d2 >= NN) return;
    atomicAdd(&g_cnt[1][d2], 1);
}

__global__ void scan_kernel() {
    __shared__ int tmp[1024];
    __shared__ int carry;
    int hop = blockIdx.x;
    int tid = threadIdx.x;
    if (tid == 0) carry = 0;
    __syncthreads();
    for (int base = 0; base < NN; base += 1024) {
        int i = base + tid;
        int v = (i < NN) ? g_cnt[hop][i] : 0;
        if (i < NN) g_cnt[hop][i] = 0;
        tmp[tid] = v;
        __syncthreads();
        for (int d = 1; d < 1024; d <<= 1) {
            int t = (tid >= d) ? tmp[tid - d] : 0;
            __syncthreads();
            tmp[tid] += t;
            __syncthreads();
        }
        int c = carry;
        if (i < NN) g_off[hop][i] = c + tmp[tid] - v;
        __syncthreads();
        if (tid == 0) carry = c + tmp[1023];
        __syncthreads();
    }
    if (tid == 0) g_off[hop][NN] = carry;
}

__global__ void fill_kernel(const void* __restrict__ ei) {
    int e = blockIdx.x * blockDim.x + threadIdx.x;
    if (e >= EE) return;
    const int is64 = g_is64;
    int s1 = edge_val(ei, e, is64);
    int d1 = edge_val(ei, EE + e, is64);
    if (s1 < 0 || s1 >= NN || d1 < 0 || d1 >= NN) return;
    int p = atomicAdd(&g_cnt[0][d1], 1);
    g_csr[0][g_off[0][d1] + p] = s1;
    int s2 = edge_val(ei, d1, is64);
    int d2 = edge_val(ei, EE + d1, is64);
    if (s2 < 0 || s2 >= NN || d2 < 0 || d2 >= NN) return;
    int p2 = atomicAdd(&g_cnt[1][d2], 1);
    g_csr[1][g_off[1][d2] + p2] = s2;
}

// -------------------- GAT aggregation: warp per dst node ----------------------
// blockIdx.y = hop. Single-pass softmax (max shift cancels exactly; logits O(1)).
// Hop 2 (hop==1) carries its self-loop TWICE (once from _get_next_hop_edges,
// once from _gat_conv's add_self_loops) -> weight 2 in numerator & denominator.
__global__ void aggregate_kernel(const float* __restrict__ b0, const float* __restrict__ b1,
                                 float* __restrict__ out) {
    int w = (blockIdx.x * blockDim.x + threadIdx.x) >> 5;
    int l = threadIdx.x & 31;
    if (w >= NN) return;
    const int hop = blockIdx.y;
    const int*   __restrict__ csr = g_csr[hop];
    const float* __restrict__ AS  = g_as[hop];
    const float* __restrict__ AD  = g_ad[hop];
    const float* bias = hop ? b1 : b0;
    const int n = w;
    const int beg = g_off[hop][n], end = g_off[hop][n + 1];
    const int head = l >> 2;
    const float self_mult = (hop == 1) ? 2.0f : 1.0f;

    float ad_l = 0.f, as_n = 0.f;
    if (l < HH) { ad_l = AD[n * HH + l]; as_n = AS[n * HH + l]; }
    float sh = (l < HH) ? self_mult * expf(lrelu(as_n + ad_l)) : 0.f;

    float pb = __shfl_sync(0xffffffffu, sh, head);
    float4 xv = *(const float4*)(g_xw + n * 256 + hop * 128 + l * 4);
    float4 acc = make_float4(pb * xv.x, pb * xv.y, pb * xv.z, pb * xv.w);

    for (int base = beg; base < end; base += 32) {
        int src = 0;
        if (base + l < end) src = csr[base + l];
        int cnt = min(32, end - base);
        for (int k = 0; k < cnt; k++) {
            int s = __shfl_sync(0xffffffffu, src, k);
            float p = 0.f;
            if (l < HH) {
                p = expf(lrelu(AS[s * HH + l] + ad_l));
                sh += p;
            }
            float pw = __shfl_sync(0xffffffffu, p, head);
            float4 mv = __ldg((const float4*)(g_xw + s * 256 + hop * 128 + l * 4));
            acc.x += pw * mv.x;
            acc.y += pw * mv.y;
            acc.z += pw * mv.z;
            acc.w += pw * mv.w;
        }
    }

    float st = __shfl_sync(0xffffffffu, sh, head);
    float inv = 1.0f / st;
    float4 bv = *(const float4*)(bias + l * 4);
    float4 o = make_float4(acc.x * inv + bv.x, acc.y * inv + bv.y,
                           acc.z * inv + bv.z, acc.w * inv + bv.w);
    *(float4*)(out + n * 256 + hop * 128 + l * 4) = o;
}

// ---------------------- residual + LayerNorm (in-place) -----------------------
__global__ void ln_kernel(const float* __restrict__ x, const float* __restrict__ gamma,
                          const float* __restrict__ beta, float* __restrict__ out) {
    int w = (blockIdx.x * blockDim.x + threadIdx.x) >> 5;
    int l = threadIdx.x & 31;
    if (w >= NN) return;
    const int base = w * 256 + l * 8;
    float4 h0 = *(float4*)(out + base);
    float4 h1 = *(float4*)(out + base + 4);
    float4 x0 = *(const float4*)(x + base);
    float4 x1 = *(const float4*)(x + base + 4);
    float v[8] = {h0.x + x0.x, h0.y + x0.y, h0.z + x0.z, h0.w + x0.w,
                  h1.x + x1.x, h1.y + x1.y, h1.z + x1.z, h1.w + x1.w};
    float s = 0.f;
#pragma unroll
    for (int j = 0; j < 8; j++) s += v[j];
#pragma unroll
    for (int d = 16; d; d >>= 1) s += __shfl_xor_sync(0xffffffffu, s, d);
    float mean = s * (1.0f / 256.0f);
    float q = 0.f;
#pragma unroll
    for (int j = 0; j < 8; j++) { float t = v[j] - mean; q += t * t; }
#pragma unroll
    for (int d = 16; d; d >>= 1) q += __shfl_xor_sync(0xffffffffu, q, d);
    float rstd = rsqrtf(q * (1.0f / 256.0f) + 1e-5f);
    float4 g0 = *(const float4*)(gamma + l * 8);
    float4 g1 = *(const float4*)(gamma + l * 8 + 4);
    float4 b0 = *(const float4*)(beta + l * 8);
    float4 b1 = *(const float4*)(beta + l * 8 + 4);
    float4 o0 = make_float4((v[0] - mean) * rstd * g0.x + b0.x,
                            (v[1] - mean) * rstd * g0.y + b0.y,
                            (v[2] - mean) * rstd * g0.z + b0.z,
                            (v[3] - mean) * rstd * g0.w + b0.w);
    float4 o1 = make_float4((v[4] - mean) * rstd * g1.x + b1.x,
                            (v[5] - mean) * rstd * g1.y + b1.y,
                            (v[6] - mean) * rstd * g1.z + b1.z,
                            (v[7] - mean) * rstd * g1.w + b1.w);
    *(float4*)(out + base)     = o0;
    *(float4*)(out + base + 4) = o1;
}

// ------------------------------- launcher -------------------------------------
extern "C" void kernel_launch(void* const* d_in, const int* in_sizes, int n_in,
                              void* d_out, int out_size) {
    const float* x     = (const float*)d_in[0];
    const void*  ei    = d_in[1];
    const float* W0    = (const float*)d_in[2];
    const float* as0   = (const float*)d_in[3];
    const float* ad0   = (const float*)d_in[4];
    const float* b0    = (const float*)d_in[5];
    const float* W1    = (const float*)d_in[6];
    const float* as1   = (const float*)d_in[7];
    const float* ad1   = (const float*)d_in[8];
    const float* b1    = (const float*)d_in[9];
    const float* gamma = (const float*)d_in[10];
    const float* beta  = (const float*)d_in[11];
    float* out = (float*)d_out;

    init_kernel<<<(NN + 255) / 256, 256>>>((const int*)ei);
    gemm_kernel<<<dim3((NN + 127) / 128, 2), 256>>>(x, W0, W1);
    att_kernel<<<(NN * 16 + 255) / 256, 256>>>(as0, ad0, as1, ad1);
    count_kernel<<<(EE + 255) / 256, 256>>>(ei);
    scan_kernel<<<2, 1024>>>();
    fill_kernel<<<(EE + 255) / 256, 256>>>(ei);
    aggregate_kernel<<<dim3((NN * 32 + 255) / 256, 2), 256>>>(b0, b1, out);
    ln_kernel<<<(NN * 32 + 255) / 256, 256>>>(x, gamma, beta, out);
}

// round 8
// speedup vs baseline: 1.0308x; 1.0141x over previous
#include <cuda_runtime.h>
#include <math.h>

#define NN 50000
#define EE 800000
#define HH 8

// ---------------- scratch (device globals: no allocation allowed) -------------
__device__ float g_xw[NN * 256];          // [x@W0 | x@W1], row stride 256 (1KB rows)
__device__ float g_as[2][NN * HH];        // per-node, per-head att_src logits (hop 0/1)
__device__ float g_ad[2][NN * HH];        // per-node, per-head att_dst logits
__device__ int   g_cnt[2][NN];            // counts, then cursors
__device__ int   g_off[2][NN + 1];        // CSR offsets (by dst)
__device__ int   g_csr[2][EE];            // src node per in-edge
__device__ int   g_is64;                  // 1 if edge_index is int64, 0 if int32

// ---------------------------------- utils ------------------------------------
__device__ __forceinline__ float lrelu(float v) { return v >= 0.f ? v : 0.2f * v; }

__device__ __forceinline__ int edge_val(const void* ei, int idx, int is64) {
    if (is64) return (int)((const long long*)ei)[idx];
    return ((const int*)ei)[idx];
}

// packed fp32x2 FMA: c = a*b + c elementwise on 2-lane packed fp32 (exact fp32)
__device__ __forceinline__ void ffma2(unsigned long long& c, unsigned long long a,
                                      unsigned long long b) {
    asm("fma.rn.f32x2 %0, %1, %2, %0;" : "+l"(c) : "l"(a), "l"(b));
}
__device__ __forceinline__ unsigned long long pack_dup(float a) {
    unsigned long long r;
    asm("mov.b64 %0, {%1, %1};" : "=l"(r) : "f"(a));
    return r;
}

// dtype probe + counter zeroing fused.
__global__ void init_kernel(const int* __restrict__ p) {
    int i = blockIdx.x * blockDim.x + threadIdx.x;
    if (i < NN) { g_cnt[0][i] = 0; g_cnt[1][i] = 0; }
    if (blockIdx.x == 0) {
        __shared__ int any_nonzero;
        if (threadIdx.x == 0) any_nonzero = 0;
        __syncthreads();
        int v = 0;
        for (int j = threadIdx.x; j < 2048; j += blockDim.x) v |= p[2 * j + 1];
        if (v) atomicOr(&any_nonzero, 1);
        __syncthreads();
        if (threadIdx.x == 0) g_is64 = (any_nonzero == 0) ? 1 : 0;
    }
}

// ------------------------------ SGEMM: xw = x @ [W0|W1] -----------------------
// BM=128, BN=128, BK=8, 256 threads, 8x8 per-thread tile, FFMA2 (f32x2) inner.
__global__ void __launch_bounds__(256) gemm_kernel(const float* __restrict__ A,
                                                   const float* __restrict__ W0,
                                                   const float* __restrict__ W1) {
    const float* B = blockIdx.y ? W1 : W0;   // [256][128]
    const int block_row = blockIdx.x * 128;

    __shared__ float As[8][128];
    __shared__ float Bs[8][128];

    unsigned long long acc2[8][4];
#pragma unroll
    for (int i = 0; i < 8; i++)
#pragma unroll
        for (int j = 0; j < 4; j++) acc2[i][j] = 0ull;

    const int tid = threadIdx.x;
    const int tx = tid & 15, ty = tid >> 4;
    const int a_row = tid >> 1;
    const int a_col4 = (tid & 1) * 4;
    const int b_row = tid >> 5;
    const int b_col = (tid & 31) * 4;

    for (int k0 = 0; k0 < 256; k0 += 8) {
        int gr = block_row + a_row;
        float4 av = make_float4(0.f, 0.f, 0.f, 0.f);
        if (gr < NN) av = *(const float4*)(A + gr * 256 + k0 + a_col4);
        As[a_col4 + 0][a_row] = av.x;
        As[a_col4 + 1][a_row] = av.y;
        As[a_col4 + 2][a_row] = av.z;
        As[a_col4 + 3][a_row] = av.w;
        float4 bv = *(const float4*)(B + (k0 + b_row) * 128 + b_col);
        *(float4*)&Bs[b_row][b_col] = bv;
        __syncthreads();
#pragma unroll
        for (int kk = 0; kk < 8; kk++) {
            float ar[8];
            *(float4*)&ar[0] = *(const float4*)&As[kk][ty * 8];
            *(float4*)&ar[4] = *(const float4*)&As[kk][ty * 8 + 4];
            unsigned long long br2[4];
            {
                ulonglong2 b01 = *(const ulonglong2*)&Bs[kk][tx * 8];
                ulonglong2 b23 = *(const ulonglong2*)&Bs[kk][tx * 8 + 4];
                br2[0] = b01.x; br2[1] = b01.y; br2[2] = b23.x; br2[3] = b23.y;
            }
#pragma unroll
            for (int i = 0; i < 8; i++) {
                unsigned long long aa = pack_dup(ar[i]);
                ffma2(acc2[i][0], aa, br2[0]);
                ffma2(acc2[i][1], aa, br2[1]);
                ffma2(acc2[i][2], aa, br2[2]);
                ffma2(acc2[i][3], aa, br2[3]);
            }
        }
        __syncthreads();
    }

    const int colbase = blockIdx.y * 128 + tx * 8;
#pragma unroll
    for (int i = 0; i < 8; i++) {
        int r = block_row + ty * 8 + i;
        if (r < NN) {
            *(ulonglong2*)(g_xw + r * 256 + colbase)     = make_ulonglong2(acc2[i][0], acc2[i][1]);
            *(ulonglong2*)(g_xw + r * 256 + colbase + 4) = make_ulonglong2(acc2[i][2], acc2[i][3]);
        }
    }
}

// -------------------- per-node attention dot products -------------------------
__global__ void att_kernel(const float* __restrict__ as0, const float* __restrict__ ad0,
                           const float* __restrict__ as1, const float* __restrict__ ad1) {
    int t = blockIdx.x * blockDim.x + threadIdx.x;   // t in [0, NN*16)
    if (t >= NN * 16) return;
    int h  = t & 7;
    int hp = (t >> 3) & 1;
    int n  = t >> 4;
    const float* xr = g_xw + n * 256 + hp * 128 + h * 16;
    const float* ap = (hp ? as1 : as0) + h * 16;
    const float* dp = (hp ? ad1 : ad0) + h * 16;
    float ps = 0.f, pd = 0.f;
#pragma unroll
    for (int c = 0; c < 16; c++) {
        float v = xr[c];
        ps += v * __ldg(ap + c);
        pd += v * __ldg(dp + c);
    }
    g_as[hp][n * HH + h] = ps;
    g_ad[hp][n * HH + h] = pd;
}

// ------------------------------ CSR build -------------------------------------
__global__ void count_kernel(const void* __restrict__ ei) {
    int e = blockIdx.x * blockDim.x + threadIdx.x;
    if (e >= EE) return;
    const int is64 = g_is64;
    int d1 = edge_val(ei, EE + e, is64);
    if (d1 < 0 || d1 >= NN) return;
    atomicAdd(&g_cnt[0][d1], 1);
    int d2 = edge_val(ei, EE + d1, is64);    // hop-2 dst: col[col[e]]
    if (d2 < 0 || d2 >= NN) return;
    atomicAdd(&g_cnt[1][d2], 1);
}

__global__ void scan_kernel() {
    __shared__ int tmp[1024];
    __shared__ int carry;
    int hop = blockIdx.x;
    int tid = threadIdx.x;
    if (tid == 0) carry = 0;
    __syncthreads();
    for (int base = 0; base < NN; base += 1024) {
        int i = base + tid;
        int v = (i < NN) ? g_cnt[hop][i] : 0;
        if (i < NN) g_cnt[hop][i] = 0;
        tmp[tid] = v;
        __syncthreads();
        for (int d = 1; d < 1024; d <<= 1) {
            int t = (tid >= d) ? tmp[tid - d] : 0;
            __syncthreads();
            tmp[tid] += t;
            __syncthreads();
        }
        int c = carry;
        if (i < NN) g_off[hop][i] = c + tmp[tid] - v;
        __syncthreads();
        if (tid == 0) carry = c + tmp[1023];
        __syncthreads();
    }
    if (tid == 0) g_off[hop][NN] = carry;
}

__global__ void fill_kernel(const void* __restrict__ ei) {
    int e = blockIdx.x * blockDim.x + threadIdx.x;
    if (e >= EE) return;
    const int is64 = g_is64;
    int s1 = edge_val(ei, e, is64);
    int d1 = edge_val(ei, EE + e, is64);
    if (s1 < 0 || s1 >= NN || d1 < 0 || d1 >= NN) return;
    int p = atomicAdd(&g_cnt[0][d1], 1);
    g_csr[0][g_off[0][d1] + p] = s1;
    int s2 = edge_val(ei, d1, is64);
    int d2 = edge_val(ei, EE + d1, is64);
    if (s2 < 0 || s2 >= NN || d2 < 0 || d2 >= NN) return;
    int p2 = atomicAdd(&g_cnt[1][d2], 1);
    g_csr[1][g_off[1][d2] + p2] = s2;
}

// -------------------- GAT aggregation: warp per dst node ----------------------
// blockIdx.y = hop. 4 edges per iteration; all 32 lanes (= 4 edges x 8 heads)
// compute exp weights simultaneously. Denominator kept per-lane, reduced once.
// Single-pass softmax (max shift cancels exactly; logits O(1), __expf safe).
// Hop 2 (hop==1) carries its self-loop TWICE -> weight 2 in num & denom.
__global__ void aggregate_kernel(const float* __restrict__ b0, const float* __restrict__ b1,
                                 float* __restrict__ out) {
    int w = (blockIdx.x * blockDim.x + threadIdx.x) >> 5;
    int l = threadIdx.x & 31;
    if (w >= NN) return;
    const int hop = blockIdx.y;
    const int*   __restrict__ csr = g_csr[hop];
    const float* __restrict__ AS  = g_as[hop];
    const float* __restrict__ AD  = g_ad[hop];
    const float* bias = hop ? b1 : b0;
    const int n = w;
    const int beg = g_off[hop][n], end = g_off[hop][n + 1];
    const float self_mult = (hop == 1) ? 2.0f : 1.0f;
    const int hE = l & 7;        // head owned during exp phase
    const int hC = l >> 2;       // head of this lane's channel group

    // lanes 0..7 load per-head AD/AS of node n; broadcast AD to all lanes by head
    float adv = 0.f, asv = 0.f;
    if (l < HH) { adv = AD[n * HH + l]; asv = AS[n * HH + l]; }
    float ad_all = __shfl_sync(0xffffffffu, adv, hE);   // AD[n, hE] in every lane

    // self-loop weight per head (lanes 0..7); counts twice for hop 2
    float sv = (l < HH) ? self_mult * __expf(lrelu(asv + adv)) : 0.f;
    float shacc = sv;                                   // per-lane denom accumulator

    float pb = __shfl_sync(0xffffffffu, sv, hC);
    float4 xv = *(const float4*)(g_xw + n * 256 + hop * 128 + l * 4);
    float4 acc = make_float4(pb * xv.x, pb * xv.y, pb * xv.z, pb * xv.w);

    for (int base = beg; base < end; base += 4) {
        const int nv = end - base;                      // >= 1
        int sl = 0;
        if (l < 4) sl = csr[base + min(l, nv - 1)];
        // edge group g = l>>3; all 32 lanes compute one (edge, head) weight
        int s_g = __shfl_sync(0xffffffffu, sl, l >> 3);
        float wgt = 0.f;
        if ((l >> 3) < nv) {
            float a = __ldg(AS + s_g * HH + hE);
            wgt = __expf(lrelu(a + ad_all));
        }
        shacc += wgt;
        const int cnt = min(4, nv);                     // warp-uniform
#pragma unroll
        for (int gg = 0; gg < 4; gg++) {
            if (gg < cnt) {
                float pw = __shfl_sync(0xffffffffu, wgt, gg * 8 + hC);
                int s = __shfl_sync(0xffffffffu, sl, gg);
                float4 mv = __ldg((const float4*)(g_xw + s * 256 + hop * 128 + l * 4));
                acc.x += pw * mv.x;
                acc.y += pw * mv.y;
                acc.z += pw * mv.z;
                acc.w += pw * mv.w;
            }
        }
    }

    // reduce denom: lanes {h, h+8, h+16, h+24} -> total for head h in every lane
    shacc += __shfl_xor_sync(0xffffffffu, shacc, 8);
    shacc += __shfl_xor_sync(0xffffffffu, shacc, 16);
    float st = __shfl_sync(0xffffffffu, shacc, hC);     // lane hC has (hC&7)==hC
    float inv = 1.0f / st;
    float4 bv = *(const float4*)(bias + l * 4);
    float4 o = make_float4(acc.x * inv + bv.x, acc.y * inv + bv.y,
                           acc.z * inv + bv.z, acc.w * inv + bv.w);
    *(float4*)(out + n * 256 + hop * 128 + l * 4) = o;
}

// ---------------------- residual + LayerNorm (in-place) -----------------------
__global__ void ln_kernel(const float* __restrict__ x, const float* __restrict__ gamma,
                          const float* __restrict__ beta, float* __restrict__ out) {
    int w = (blockIdx.x * blockDim.x + threadIdx.x) >> 5;
    int l = threadIdx.x & 31;
    if (w >= NN) return;
    const int base = w * 256 + l * 8;
    float4 h0 = *(float4*)(out + base);
    float4 h1 = *(float4*)(out + base + 4);
    float4 x0 = *(const float4*)(x + base);
    float4 x1 = *(const float4*)(x + base + 4);
    float v[8] = {h0.x + x0.x, h0.y + x0.y, h0.z + x0.z, h0.w + x0.w,
                  h1.x + x1.x, h1.y + x1.y, h1.z + x1.z, h1.w + x1.w};
    float s = 0.f;
#pragma unroll
    for (int j = 0; j < 8; j++) s += v[j];
#pragma unroll
    for (int d = 16; d; d >>= 1) s += __shfl_xor_sync(0xffffffffu, s, d);
    float mean = s * (1.0f / 256.0f);
    float q = 0.f;
#pragma unroll
    for (int j = 0; j < 8; j++) { float t = v[j] - mean; q += t * t; }
#pragma unroll
    for (int d = 16; d; d >>= 1) q += __shfl_xor_sync(0xffffffffu, q, d);
    float rstd = rsqrtf(q * (1.0f / 256.0f) + 1e-5f);
    float4 g0 = *(const float4*)(gamma + l * 8);
    float4 g1 = *(const float4*)(gamma + l * 8 + 4);
    float4 b0 = *(const float4*)(beta + l * 8);
    float4 b1 = *(const float4*)(beta + l * 8 + 4);
    float4 o0 = make_float4((v[0] - mean) * rstd * g0.x + b0.x,
                            (v[1] - mean) * rstd * g0.y + b0.y,
                            (v[2] - mean) * rstd * g0.z + b0.z,
                            (v[3] - mean) * rstd * g0.w + b0.w);
    float4 o1 = make_float4((v[4] - mean) * rstd * g1.x + b1.x,
                            (v[5] - mean) * rstd * g1.y + b1.y,
                            (v[6] - mean) * rstd * g1.z + b1.z,
                            (v[7] - mean) * rstd * g1.w + b1.w);
    *(float4*)(out + base)     = o0;
    *(float4*)(out + base + 4) = o1;
}

// ------------------------------- launcher -------------------------------------
// Order puts gemm_kernel 4th: ncu's fixed capture slot (observed R6/R7) lands on
// it, giving us the GEMM profile. All data dependencies still respected.
extern "C" void kernel_launch(void* const* d_in, const int* in_sizes, int n_in,
                              void* d_out, int out_size) {
    const float* x     = (const float*)d_in[0];
    const void*  ei    = d_in[1];
    const float* W0    = (const float*)d_in[2];
    const float* as0   = (const float*)d_in[3];
    const float* ad0   = (const float*)d_in[4];
    const float* b0    = (const float*)d_in[5];
    const float* W1    = (const float*)d_in[6];
    const float* as1   = (const float*)d_in[7];
    const float* ad1   = (const float*)d_in[8];
    const float* b1    = (const float*)d_in[9];
    const float* gamma = (const float*)d_in[10];
    const float* beta  = (const float*)d_in[11];
    float* out = (float*)d_out;

    init_kernel<<<(NN + 255) / 256, 256>>>((const int*)ei);
    count_kernel<<<(EE + 255) / 256, 256>>>(ei);
    scan_kernel<<<2, 1024>>>();
    gemm_kernel<<<dim3((NN + 127) / 128, 2), 256>>>(x, W0, W1);      // <- profiled slot
    fill_kernel<<<(EE + 255) / 256, 256>>>(ei);
    att_kernel<<<(NN * 16 + 255) / 256, 256>>>(as0, ad0, as1, ad1);
    aggregate_kernel<<<dim3((NN * 32 + 255) / 256, 2), 256>>>(b0, b1, out);
    ln_kernel<<<(NN * 32 + 255) / 256, 256>>>(x, gamma, beta, out);
}

// round 12
// speedup vs baseline: 1.3613x; 1.3207x over previous
#include <cuda_runtime.h>
#include <cuda_bf16.h>
#include <math.h>
#include <stdint.h>

#define NN 50000
#define EE 800000
#define HH 8

// ---------------- scratch (device globals: no allocation allowed) -------------
__device__ float g_xw[NN * 256];          // [x@W0 | x@W1], row stride 256
__device__ float g_as[2][NN * HH];
__device__ float g_ad[2][NN * HH];
__device__ int   g_cnt[2][NN];
__device__ int   g_off[2][NN + 1];
__device__ int   g_csr[2][EE];
__device__ int   g_is64;

// ---------------------------------- utils ------------------------------------
__device__ __forceinline__ float lrelu(float v) { return v >= 0.f ? v : 0.2f * v; }

__device__ __forceinline__ int edge_val(const void* ei, int idx, int is64) {
    if (is64) return (int)((const long long*)ei)[idx];
    return ((const int*)ei)[idx];
}

// fp32 -> bf16 hi + bf16(residual) lo, 4 lanes packed as 2x uint2
__device__ __forceinline__ void cvt_hi_lo4(float4 v, uint2& hi, uint2& lo) {
    float f[4] = {v.x, v.y, v.z, v.w};
    unsigned short hs[4], ls[4];
#pragma unroll
    for (int i = 0; i < 4; i++) {
        __nv_bfloat16 h = __float2bfloat16(f[i]);
        hs[i] = __bfloat16_as_ushort(h);
        float r = f[i] - __bfloat162float(h);
        ls[i] = __bfloat16_as_ushort(__float2bfloat16(r));
    }
    hi = make_uint2((uint32_t)hs[0] | ((uint32_t)hs[1] << 16), (uint32_t)hs[2] | ((uint32_t)hs[3] << 16));
    lo = make_uint2((uint32_t)ls[0] | ((uint32_t)ls[1] << 16), (uint32_t)ls[2] | ((uint32_t)ls[3] << 16));
}

// dtype probe + counter zeroing fused.
__global__ void init_kernel(const int* __restrict__ p) {
    int i = blockIdx.x * blockDim.x + threadIdx.x;
    if (i < NN) { g_cnt[0][i] = 0; g_cnt[1][i] = 0; }
    if (blockIdx.x == 0) {
        __shared__ int any_nonzero;
        if (threadIdx.x == 0) any_nonzero = 0;
        __syncthreads();
        int v = 0;
        for (int j = threadIdx.x; j < 2048; j += blockDim.x) v |= p[2 * j + 1];
        if (v) atomicOr(&any_nonzero, 1);
        __syncthreads();
        if (threadIdx.x == 0) g_is64 = (any_nonzero == 0) ? 1 : 0;
    }
}

// --------------- tensor-core GEMM: g_xw = x @ [W0|W1], bf16 3x split ----------
// mma.sync m16n8k16 bf16 (sm_80 PTX -> legal on plain sm_103 target).
// CTA: 128 rows x 128 cols (blockIdx.y picks W0/W1). K=256 in 4 chunks of 64.
// SMEM rows padded to 144B: fragment LDS bank = 4*(lane>>2)+(lane&3) -> all 32
// banks distinct, conflict-free.
#define ROWB 144
#define SMA_H 0
#define SMA_L 18432
#define SMB_H 36864
#define SMB_L 55296
#define SM_GEMM_TOTAL 73728

__device__ __forceinline__ uint32_t lds32(const char* base, int row, int col) {
    return *(const uint32_t*)(base + row * ROWB + col * 2);
}
__device__ __forceinline__ void mma16816(float* c, const uint32_t* a, const uint32_t* b) {
    asm volatile(
        "mma.sync.aligned.m16n8k16.row.col.f32.bf16.bf16.f32 "
        "{%0,%1,%2,%3}, {%4,%5,%6,%7}, {%8,%9}, {%0,%1,%2,%3};"
        : "+f"(c[0]), "+f"(c[1]), "+f"(c[2]), "+f"(c[3])
        : "r"(a[0]), "r"(a[1]), "r"(a[2]), "r"(a[3]), "r"(b[0]), "r"(b[1]));
}

__global__ void __launch_bounds__(256) tc_gemm_kernel(const float* __restrict__ X,
                                                      const float* __restrict__ W0,
                                                      const float* __restrict__ W1) {
    extern __shared__ char smem[];
    const int tid = threadIdx.x, lane = tid & 31, wid = tid >> 5;
    const int m0 = blockIdx.x * 128;
    const float* W = blockIdx.y ? W1 : W0;       // [256][128]
    const int wm = (wid & 1) * 64;               // warp m-offset
    const int wn = (wid >> 1) * 32;              // warp n-offset

    float c[4][4][4];
#pragma unroll
    for (int a = 0; a < 4; a++)
#pragma unroll
        for (int b = 0; b < 4; b++)
#pragma unroll
            for (int d = 0; d < 4; d++) c[a][b][d] = 0.f;

    const int r0 = lane >> 2;          // fragment row within 8
    const int c0 = (lane & 3) * 2;     // fragment k-col pair

    for (int chunk = 0; chunk < 4; chunk++) {
        const int k0 = chunk * 64;
        // load A chunk: 128 rows x 64 k, split hi/lo
        for (int it = tid; it < 128 * 16; it += 256) {
            int r = it >> 4, q = it & 15;
            float4 v = make_float4(0.f, 0.f, 0.f, 0.f);
            if (m0 + r < NN) v = *(const float4*)(X + (m0 + r) * 256 + k0 + q * 4);
            uint2 hi, lo;
            cvt_hi_lo4(v, hi, lo);
            *(uint2*)(smem + SMA_H + r * ROWB + q * 8) = hi;
            *(uint2*)(smem + SMA_L + r * ROWB + q * 8) = lo;
        }
        // load B chunk: B[n][k] = W[k0+k][n], 128 n x 64 k, split hi/lo
        for (int it = tid; it < 128 * 16; it += 256) {
            int n = it & 127, q = it >> 7;
            int kb = k0 + q * 4;
            float4 v = make_float4(__ldg(W + (kb + 0) * 128 + n), __ldg(W + (kb + 1) * 128 + n),
                                   __ldg(W + (kb + 2) * 128 + n), __ldg(W + (kb + 3) * 128 + n));
            uint2 hi, lo;
            cvt_hi_lo4(v, hi, lo);
            *(uint2*)(smem + SMB_H + n * ROWB + q * 8) = hi;
            *(uint2*)(smem + SMB_L + n * ROWB + q * 8) = lo;
        }
        __syncthreads();

#pragma unroll
        for (int ks = 0; ks < 4; ks++) {
            const int kb = ks * 16;
            uint32_t aH[4][4], aL[4][4];
#pragma unroll
            for (int mf = 0; mf < 4; mf++) {
                int rb = wm + mf * 16;
                aH[mf][0] = lds32(smem + SMA_H, rb + r0,     kb + c0);
                aH[mf][1] = lds32(smem + SMA_H, rb + r0 + 8, kb + c0);
                aH[mf][2] = lds32(smem + SMA_H, rb + r0,     kb + c0 + 8);
                aH[mf][3] = lds32(smem + SMA_H, rb + r0 + 8, kb + c0 + 8);
                aL[mf][0] = lds32(smem + SMA_L, rb + r0,     kb + c0);
                aL[mf][1] = lds32(smem + SMA_L, rb + r0 + 8, kb + c0);
                aL[mf][2] = lds32(smem + SMA_L, rb + r0,     kb + c0 + 8);
                aL[mf][3] = lds32(smem + SMA_L, rb + r0 + 8, kb + c0 + 8);
            }
            uint32_t bH[4][2], bL[4][2];
#pragma unroll
            for (int nf = 0; nf < 4; nf++) {
                int nb = wn + nf * 8 + r0;
                bH[nf][0] = lds32(smem + SMB_H, nb, kb + c0);
                bH[nf][1] = lds32(smem + SMB_H, nb, kb + c0 + 8);
                bL[nf][0] = lds32(smem + SMB_L, nb, kb + c0);
                bL[nf][1] = lds32(smem + SMB_L, nb, kb + c0 + 8);
            }
#pragma unroll
            for (int mf = 0; mf < 4; mf++)
#pragma unroll
                for (int nf = 0; nf < 4; nf++) {
                    mma16816(c[mf][nf], aH[mf], bH[nf]);
                    mma16816(c[mf][nf], aH[mf], bL[nf]);
                    mma16816(c[mf][nf], aL[mf], bH[nf]);
                }
        }
        __syncthreads();
    }

    const int colb = blockIdx.y * 128 + wn;
#pragma unroll
    for (int mf = 0; mf < 4; mf++) {
        int gr = m0 + wm + mf * 16 + r0;
#pragma unroll
        for (int nf = 0; nf < 4; nf++) {
            int gc = colb + nf * 8 + c0;
            if (gr < NN)     *(float2*)(g_xw + gr * 256 + gc)       = make_float2(c[mf][nf][0], c[mf][nf][1]);
            if (gr + 8 < NN) *(float2*)(g_xw + (gr + 8) * 256 + gc) = make_float2(c[mf][nf][2], c[mf][nf][3]);
        }
    }
}

// -------------------- per-node attention dot products -------------------------
__global__ void att_kernel(const float* __restrict__ as0, const float* __restrict__ ad0,
                           const float* __restrict__ as1, const float* __restrict__ ad1) {
    int t = blockIdx.x * blockDim.x + threadIdx.x;
    if (t >= NN * 16) return;
    int h  = t & 7;
    int hp = (t >> 3) & 1;
    int n  = t >> 4;
    const float* xr = g_xw + n * 256 + hp * 128 + h * 16;
    const float* ap = (hp ? as1 : as0) + h * 16;
    const float* dp = (hp ? ad1 : ad0) + h * 16;
    float ps = 0.f, pd = 0.f;
#pragma unroll
    for (int c = 0; c < 16; c++) {
        float v = xr[c];
        ps += v * __ldg(ap + c);
        pd += v * __ldg(dp + c);
    }
    g_as[hp][n * HH + h] = ps;
    g_ad[hp][n * HH + h] = pd;
}

// ------------------------------ CSR build -------------------------------------
__global__ void count_kernel(const void* __restrict__ ei) {
    int e = blockIdx.x * blockDim.x + threadIdx.x;
    if (e >= EE) return;
    const int is64 = g_is64;
    int d1 = edge_val(ei, EE + e, is64);
    if (d1 < 0 || d1 >= NN) return;
    atomicAdd(&g_cnt[0][d1], 1);
    int d2 = edge_val(ei, EE + d1, is64);
    if (d2 < 0 || d2 >= NN) return;
    atomicAdd(&g_cnt[1][d2], 1);
}

__global__ void scan_kernel() {
    __shared__ int tmp[1024];
    __shared__ int carry;
    int hop = blockIdx.x;
    int tid = threadIdx.x;
    if (tid == 0) carry = 0;
    __syncthreads();
    for (int base = 0; base < NN; base += 1024) {
        int i = base + tid;
        int v = (i < NN) ? g_cnt[hop][i] : 0;
        if (i < NN) g_cnt[hop][i] = 0;
        tmp[tid] = v;
        __syncthreads();
        for (int d = 1; d < 1024; d <<= 1) {
            int t = (tid >= d) ? tmp[tid - d] : 0;
            __syncthreads();
            tmp[tid] += t;
            __syncthreads();
        }
        int c = carry;
        if (i < NN) g_off[hop][i] = c + tmp[tid] - v;
        __syncthreads();
        if (tid == 0) carry = c + tmp[1023];
        __syncthreads();
    }
    if (tid == 0) g_off[hop][NN] = carry;
}

__global__ void fill_kernel(const void* __restrict__ ei) {
    int e = blockIdx.x * blockDim.x + threadIdx.x;
    if (e >= EE) return;
    const int is64 = g_is64;
    int s1 = edge_val(ei, e, is64);
    int d1 = edge_val(ei, EE + e, is64);
    if (s1 < 0 || s1 >= NN || d1 < 0 || d1 >= NN) return;
    int p = atomicAdd(&g_cnt[0][d1], 1);
    g_csr[0][g_off[0][d1] + p] = s1;
    int s2 = edge_val(ei, d1, is64);
    int d2 = edge_val(ei, EE + d1, is64);
    if (s2 < 0 || s2 >= NN || d2 < 0 || d2 >= NN) return;
    int p2 = atomicAdd(&g_cnt[1][d2], 1);
    g_csr[1][g_off[1][d2] + p2] = s2;
}

// -------------------- GAT aggregation: warp per dst node ----------------------
// 8 edges/iteration (2 exp rounds of 4 edges x 8 heads), MLP~8 on gathers.
// Hop 2 self-loop counted twice (reference duplicates it).
__global__ void aggregate_kernel(const float* __restrict__ b0, const float* __restrict__ b1,
                                 float* __restrict__ out) {
    int w = (blockIdx.x * blockDim.x + threadIdx.x) >> 5;
    int l = threadIdx.x & 31;
    if (w >= NN) return;
    const int hop = blockIdx.y;
    const int*   __restrict__ csr = g_csr[hop];
    const float* __restrict__ AS  = g_as[hop];
    const float* __restrict__ AD  = g_ad[hop];
    const float* bias = hop ? b1 : b0;
    const int n = w;
    const int beg = g_off[hop][n], end = g_off[hop][n + 1];
    const float self_mult = (hop == 1) ? 2.0f : 1.0f;
    const int hE = l & 7;
    const int hC = l >> 2;

    float adv = 0.f, asv = 0.f;
    if (l < HH) { adv = AD[n * HH + l]; asv = AS[n * HH + l]; }
    float ad_all = __shfl_sync(0xffffffffu, adv, hE);

    float sv = (l < HH) ? self_mult * __expf(lrelu(asv + adv)) : 0.f;
    float shacc = sv;

    float pb = __shfl_sync(0xffffffffu, sv, hC);
    float4 xv = *(const float4*)(g_xw + n * 256 + hop * 128 + l * 4);
    float4 acc = make_float4(pb * xv.x, pb * xv.y, pb * xv.z, pb * xv.w);

    for (int base = beg; base < end; base += 8) {
        const int nv = end - base;
        int sl = 0;
        if (l < 8) sl = csr[base + min(l, nv - 1)];
        const int eg = l >> 3;
        int s0 = __shfl_sync(0xffffffffu, sl, eg);
        int s1 = __shfl_sync(0xffffffffu, sl, 4 + eg);
        float wgt0 = 0.f, wgt1 = 0.f;
        if (eg < nv)     wgt0 = __expf(lrelu(__ldg(AS + s0 * HH + hE) + ad_all));
        if (4 + eg < nv) wgt1 = __expf(lrelu(__ldg(AS + s1 * HH + hE) + ad_all));
        shacc += wgt0 + wgt1;
        const int cnt = min(8, nv);
#pragma unroll
        for (int gg = 0; gg < 8; gg++) {
            if (gg < cnt) {
                float pw = __shfl_sync(0xffffffffu, (gg < 4) ? wgt0 : wgt1, (gg & 3) * 8 + hC);
                int s = __shfl_sync(0xffffffffu, sl, gg);
                float4 mv = __ldg((const float4*)(g_xw + s * 256 + hop * 128 + l * 4));
                acc.x += pw * mv.x;
                acc.y += pw * mv.y;
                acc.z += pw * mv.z;
                acc.w += pw * mv.w;
            }
        }
    }

    shacc += __shfl_xor_sync(0xffffffffu, shacc, 8);
    shacc += __shfl_xor_sync(0xffffffffu, shacc, 16);
    float st = __shfl_sync(0xffffffffu, shacc, hC);
    float inv = 1.0f / st;
    float4 bv = *(const float4*)(bias + l * 4);
    float4 o = make_float4(acc.x * inv + bv.x, acc.y * inv + bv.y,
                           acc.z * inv + bv.z, acc.w * inv + bv.w);
    *(float4*)(out + n * 256 + hop * 128 + l * 4) = o;
}

// ---------------------- residual + LayerNorm (in-place) -----------------------
__global__ void ln_kernel(const float* __restrict__ x, const float* __restrict__ gamma,
                          const float* __restrict__ beta, float* __restrict__ out) {
    int w = (blockIdx.x * blockDim.x + threadIdx.x) >> 5;
    int l = threadIdx.x & 31;
    if (w >= NN) return;
    const int base = w * 256 + l * 8;
    float4 h0 = *(float4*)(out + base);
    float4 h1 = *(float4*)(out + base + 4);
    float4 x0 = *(const float4*)(x + base);
    float4 x1 = *(const float4*)(x + base + 4);
    float v[8] = {h0.x + x0.x, h0.y + x0.y, h0.z + x0.z, h0.w + x0.w,
                  h1.x + x1.x, h1.y + x1.y, h1.z + x1.z, h1.w + x1.w};
    float s = 0.f;
#pragma unroll
    for (int j = 0; j < 8; j++) s += v[j];
#pragma unroll
    for (int d = 16; d; d >>= 1) s += __shfl_xor_sync(0xffffffffu, s, d);
    float mean = s * (1.0f / 256.0f);
    float q = 0.f;
#pragma unroll
    for (int j = 0; j < 8; j++) { float t = v[j] - mean; q += t * t; }
#pragma unroll
    for (int d = 16; d; d >>= 1) q += __shfl_xor_sync(0xffffffffu, q, d);
    float rstd = rsqrtf(q * (1.0f / 256.0f) + 1e-5f);
    float4 g0 = *(const float4*)(gamma + l * 8);
    float4 g1 = *(const float4*)(gamma + l * 8 + 4);
    float4 b0 = *(const float4*)(beta + l * 8);
    float4 b1 = *(const float4*)(beta + l * 8 + 4);
    float4 o0 = make_float4((v[0] - mean) * rstd * g0.x + b0.x,
                            (v[1] - mean) * rstd * g0.y + b0.y,
                            (v[2] - mean) * rstd * g0.z + b0.z,
                            (v[3] - mean) * rstd * g0.w + b0.w);
    float4 o1 = make_float4((v[4] - mean) * rstd * g1.x + b1.x,
                            (v[5] - mean) * rstd * g1.y + b1.y,
                            (v[6] - mean) * rstd * g1.z + b1.z,
                            (v[7] - mean) * rstd * g1.w + b1.w);
    *(float4*)(out + base)     = o0;
    *(float4*)(out + base + 4) = o1;
}

// ------------------------------- launcher -------------------------------------
extern "C" void kernel_launch(void* const* d_in, const int* in_sizes, int n_in,
                              void* d_out, int out_size) {
    const float* x     = (const float*)d_in[0];
    const void*  ei    = d_in[1];
    const float* W0    = (const float*)d_in[2];
    const float* as0   = (const float*)d_in[3];
    const float* ad0   = (const float*)d_in[4];
    const float* b0    = (const float*)d_in[5];
    const float* W1    = (const float*)d_in[6];
    const float* as1   = (const float*)d_in[7];
    const float* ad1   = (const float*)d_in[8];
    const float* b1    = (const float*)d_in[9];
    const float* gamma = (const float*)d_in[10];
    const float* beta  = (const float*)d_in[11];
    float* out = (float*)d_out;

    cudaFuncSetAttribute(tc_gemm_kernel, cudaFuncAttributeMaxDynamicSharedMemorySize, SM_GEMM_TOTAL);

    init_kernel<<<(NN + 255) / 256, 256>>>((const int*)ei);
    count_kernel<<<(EE + 255) / 256, 256>>>(ei);
    scan_kernel<<<2, 1024>>>();
    tc_gemm_kernel<<<dim3((NN + 127) / 128, 2), 256, SM_GEMM_TOTAL>>>(x, W0, W1);  // profiled slot
    fill_kernel<<<(EE + 255) / 256, 256>>>(ei);
    att_kernel<<<(NN * 16 + 255) / 256, 256>>>(as0, ad0, as1, ad1);
    aggregate_kernel<<<dim3((NN * 32 + 255) / 256, 2), 256>>>(b0, b1, out);
    ln_kernel<<<(NN * 32 + 255) / 256, 256>>>(x, gamma, beta, out);
}

// round 14
// speedup vs baseline: 1.5652x; 1.1498x over previous
#include <cuda_runtime.h>
#include <cuda_bf16.h>
#include <math.h>
#include <stdint.h>

#define NN 50000
#define EE 800000
#define HH 8

// ---------------- scratch (device globals: no allocation allowed) -------------
__device__ float g_xw[NN * 256];          // [x@W0 | x@W1], row stride 256
__device__ float g_as[2][NN * HH];
__device__ float g_ad[2][NN * HH];
__device__ int   g_cnt[2][NN];
__device__ int   g_off[2][NN + 1];
__device__ int   g_csr[2][EE];
__device__ int   g_is64;

// ---------------------------------- utils ------------------------------------
__device__ __forceinline__ float lrelu(float v) { return v >= 0.f ? v : 0.2f * v; }

__device__ __forceinline__ int edge_val(const void* ei, int idx, int is64) {
    if (is64) return (int)((const long long*)ei)[idx];
    return ((const int*)ei)[idx];
}

// fp32 -> bf16 hi + bf16(residual) lo, 4 lanes packed as 2x uint2
__device__ __forceinline__ void cvt_hi_lo4(float4 v, uint2& hi, uint2& lo) {
    float f[4] = {v.x, v.y, v.z, v.w};
    unsigned short hs[4], ls[4];
#pragma unroll
    for (int i = 0; i < 4; i++) {
        __nv_bfloat16 h = __float2bfloat16(f[i]);
        hs[i] = __bfloat16_as_ushort(h);
        float r = f[i] - __bfloat162float(h);
        ls[i] = __bfloat16_as_ushort(__float2bfloat16(r));
    }
    hi = make_uint2((uint32_t)hs[0] | ((uint32_t)hs[1] << 16), (uint32_t)hs[2] | ((uint32_t)hs[3] << 16));
    lo = make_uint2((uint32_t)ls[0] | ((uint32_t)ls[1] << 16), (uint32_t)ls[2] | ((uint32_t)ls[3] << 16));
}

// dtype probe + counter zeroing fused.
__global__ void init_kernel(const int* __restrict__ p) {
    int i = blockIdx.x * blockDim.x + threadIdx.x;
    if (i < NN) { g_cnt[0][i] = 0; g_cnt[1][i] = 0; }
    if (blockIdx.x == 0) {
        __shared__ int any_nonzero;
        if (threadIdx.x == 0) any_nonzero = 0;
        __syncthreads();
        int v = 0;
        for (int j = threadIdx.x; j < 2048; j += blockDim.x) v |= p[2 * j + 1];
        if (v) atomicOr(&any_nonzero, 1);
        __syncthreads();
        if (threadIdx.x == 0) g_is64 = (any_nonzero == 0) ? 1 : 0;
    }
}

// --------------- tensor-core GEMM: g_xw = x @ [W0|W1], bf16 3x split ----------
// mma.sync m16n8k16 bf16. CTA: 128 rows x 128 cols (blockIdx.y picks hop).
// Epilogue computes the per-node attention logits for this CTA's rows/hop
// (att_kernel fused: rows m0..m0+127 x cols hop*128..+128 are exactly here).
#define ROWB 144
#define SMA_H 0
#define SMA_L 18432
#define SMB_H 36864
#define SMB_L 55296
#define SM_GEMM_TOTAL 73728

__device__ __forceinline__ uint32_t lds32(const char* base, int row, int col) {
    return *(const uint32_t*)(base + row * ROWB + col * 2);
}
__device__ __forceinline__ void mma16816(float* c, const uint32_t* a, const uint32_t* b) {
    asm volatile(
        "mma.sync.aligned.m16n8k16.row.col.f32.bf16.bf16.f32 "
        "{%0,%1,%2,%3}, {%4,%5,%6,%7}, {%8,%9}, {%0,%1,%2,%3};"
        : "+f"(c[0]), "+f"(c[1]), "+f"(c[2]), "+f"(c[3])
        : "r"(a[0]), "r"(a[1]), "r"(a[2]), "r"(a[3]), "r"(b[0]), "r"(b[1]));
}

__global__ void __launch_bounds__(256) tc_gemm_kernel(const float* __restrict__ X,
                                                      const float* __restrict__ W0,
                                                      const float* __restrict__ W1,
                                                      const float* __restrict__ as0,
                                                      const float* __restrict__ ad0,
                                                      const float* __restrict__ as1,
                                                      const float* __restrict__ ad1) {
    extern __shared__ char smem[];
    const int tid = threadIdx.x, lane = tid & 31, wid = tid >> 5;
    const int m0 = blockIdx.x * 128;
    const int hop = blockIdx.y;
    const float* W = hop ? W1 : W0;              // [256][128]
    const int wm = (wid & 1) * 64;
    const int wn = (wid >> 1) * 32;

    float c[4][4][4];
#pragma unroll
    for (int a = 0; a < 4; a++)
#pragma unroll
        for (int b = 0; b < 4; b++)
#pragma unroll
            for (int d = 0; d < 4; d++) c[a][b][d] = 0.f;

    const int r0 = lane >> 2;
    const int c0 = (lane & 3) * 2;

    for (int chunk = 0; chunk < 4; chunk++) {
        const int k0 = chunk * 64;
        for (int it = tid; it < 128 * 16; it += 256) {
            int r = it >> 4, q = it & 15;
            float4 v = make_float4(0.f, 0.f, 0.f, 0.f);
            if (m0 + r < NN) v = *(const float4*)(X + (m0 + r) * 256 + k0 + q * 4);
            uint2 hi, lo;
            cvt_hi_lo4(v, hi, lo);
            *(uint2*)(smem + SMA_H + r * ROWB + q * 8) = hi;
            *(uint2*)(smem + SMA_L + r * ROWB + q * 8) = lo;
        }
        for (int it = tid; it < 128 * 16; it += 256) {
            int n = it & 127, q = it >> 7;
            int kb = k0 + q * 4;
            float4 v = make_float4(__ldg(W + (kb + 0) * 128 + n), __ldg(W + (kb + 1) * 128 + n),
                                   __ldg(W + (kb + 2) * 128 + n), __ldg(W + (kb + 3) * 128 + n));
            uint2 hi, lo;
            cvt_hi_lo4(v, hi, lo);
            *(uint2*)(smem + SMB_H + n * ROWB + q * 8) = hi;
            *(uint2*)(smem + SMB_L + n * ROWB + q * 8) = lo;
        }
        __syncthreads();

#pragma unroll
        for (int ks = 0; ks < 4; ks++) {
            const int kb = ks * 16;
            uint32_t aH[4][4], aL[4][4];
#pragma unroll
            for (int mf = 0; mf < 4; mf++) {
                int rb = wm + mf * 16;
                aH[mf][0] = lds32(smem + SMA_H, rb + r0,     kb + c0);
                aH[mf][1] = lds32(smem + SMA_H, rb + r0 + 8, kb + c0);
                aH[mf][2] = lds32(smem + SMA_H, rb + r0,     kb + c0 + 8);
                aH[mf][3] = lds32(smem + SMA_H, rb + r0 + 8, kb + c0 + 8);
                aL[mf][0] = lds32(smem + SMA_L, rb + r0,     kb + c0);
                aL[mf][1] = lds32(smem + SMA_L, rb + r0 + 8, kb + c0);
                aL[mf][2] = lds32(smem + SMA_L, rb + r0,     kb + c0 + 8);
                aL[mf][3] = lds32(smem + SMA_L, rb + r0 + 8, kb + c0 + 8);
            }
            uint32_t bH[4][2], bL[4][2];
#pragma unroll
            for (int nf = 0; nf < 4; nf++) {
                int nb = wn + nf * 8 + r0;
                bH[nf][0] = lds32(smem + SMB_H, nb, kb + c0);
                bH[nf][1] = lds32(smem + SMB_H, nb, kb + c0 + 8);
                bL[nf][0] = lds32(smem + SMB_L, nb, kb + c0);
                bL[nf][1] = lds32(smem + SMB_L, nb, kb + c0 + 8);
            }
#pragma unroll
            for (int mf = 0; mf < 4; mf++)
#pragma unroll
                for (int nf = 0; nf < 4; nf++) {
                    mma16816(c[mf][nf], aH[mf], bH[nf]);
                    mma16816(c[mf][nf], aH[mf], bL[nf]);
                    mma16816(c[mf][nf], aL[mf], bH[nf]);
                }
        }
        __syncthreads();
    }

    const int colb = hop * 128 + wn;
#pragma unroll
    for (int mf = 0; mf < 4; mf++) {
        int gr = m0 + wm + mf * 16 + r0;
#pragma unroll
        for (int nf = 0; nf < 4; nf++) {
            int gc = colb + nf * 8 + c0;
            if (gr < NN)     *(float2*)(g_xw + gr * 256 + gc)       = make_float2(c[mf][nf][0], c[mf][nf][1]);
            if (gr + 8 < NN) *(float2*)(g_xw + (gr + 8) * 256 + gc) = make_float2(c[mf][nf][2], c[mf][nf][3]);
        }
    }

    // ---- fused attention logits for this CTA's 128 rows, this hop ----
    __syncthreads();   // order our global g_xw writes before CTA-local reads
    const float* ap = hop ? as1 : as0;
    const float* dp = hop ? ad1 : ad0;
    for (int it = tid; it < 128 * 8; it += 256) {
        int r = it >> 3, h = it & 7;
        int n = m0 + r;
        if (n < NN) {
            const float* xr = g_xw + n * 256 + hop * 128 + h * 16;
            float ps = 0.f, pd = 0.f;
#pragma unroll
            for (int cc = 0; cc < 16; cc++) {
                float v = xr[cc];
                ps += v * __ldg(ap + h * 16 + cc);
                pd += v * __ldg(dp + h * 16 + cc);
            }
            g_as[hop][n * HH + h] = ps;
            g_ad[hop][n * HH + h] = pd;
        }
    }
}

// ------------------------------ CSR build -------------------------------------
__global__ void count_kernel(const void* __restrict__ ei) {
    int e = blockIdx.x * blockDim.x + threadIdx.x;
    if (e >= EE) return;
    const int is64 = g_is64;
    int d1 = edge_val(ei, EE + e, is64);
    if (d1 < 0 || d1 >= NN) return;
    atomicAdd(&g_cnt[0][d1], 1);
    int d2 = edge_val(ei, EE + d1, is64);
    if (d2 < 0 || d2 >= NN) return;
    atomicAdd(&g_cnt[1][d2], 1);
}

// exclusive scan per hop: warp-shuffle scan, 4 barriers per 1024-tile.
__global__ void scan_kernel() {
    __shared__ int warp_sums[32];
    __shared__ int carry_s;
    const int hop = blockIdx.x;
    const int tid = threadIdx.x;
    const int lane = tid & 31, wrp = tid >> 5;
    if (tid == 0) carry_s = 0;
    __syncthreads();
    for (int base = 0; base < NN; base += 1024) {
        int i = base + tid;
        int v = (i < NN) ? g_cnt[hop][i] : 0;
        if (i < NN) g_cnt[hop][i] = 0;
        int s = v;
#pragma unroll
        for (int d = 1; d < 32; d <<= 1) {
            int t = __shfl_up_sync(0xffffffffu, s, d);
            if (lane >= d) s += t;
        }
        if (lane == 31) warp_sums[wrp] = s;
        __syncthreads();
        if (wrp == 0) {
            int ws = warp_sums[lane];
#pragma unroll
            for (int d = 1; d < 32; d <<= 1) {
                int t = __shfl_up_sync(0xffffffffu, ws, d);
                if (lane >= d) ws += t;
            }
            warp_sums[lane] = ws;
        }
        __syncthreads();
        int excl = (wrp ? warp_sums[wrp - 1] : 0) + (s - v);
        int cbase = carry_s;
        if (i < NN) g_off[hop][i] = cbase + excl;
        int total = warp_sums[31];
        __syncthreads();                       // all consumed carry_s
        if (tid == 0) carry_s = cbase + total;
        __syncthreads();
    }
    if (tid == 0) g_off[hop][NN] = carry_s;
}

__global__ void fill_kernel(const void* __restrict__ ei) {
    int e = blockIdx.x * blockDim.x + threadIdx.x;
    if (e >= EE) return;
    const int is64 = g_is64;
    int s1 = edge_val(ei, e, is64);
    int d1 = edge_val(ei, EE + e, is64);
    if (s1 < 0 || s1 >= NN || d1 < 0 || d1 >= NN) return;
    int p = atomicAdd(&g_cnt[0][d1], 1);
    g_csr[0][g_off[0][d1] + p] = s1;
    int s2 = edge_val(ei, d1, is64);
    int d2 = edge_val(ei, EE + d1, is64);
    if (s2 < 0 || s2 >= NN || d2 < 0 || d2 >= NN) return;
    int p2 = atomicAdd(&g_cnt[1][d2], 1);
    g_csr[1][g_off[1][d2] + p2] = s2;
}

// -------------------- GAT aggregation: warp per dst node ----------------------
// 16 edges/iteration (4 exp rounds of 4 edges x 8 heads), MLP~16 on gathers.
// Hop 2 self-loop counted twice (reference duplicates it).
__global__ void aggregate_kernel(const float* __restrict__ b0, const float* __restrict__ b1,
                                 float* __restrict__ out) {
    int w = (blockIdx.x * blockDim.x + threadIdx.x) >> 5;
    int l = threadIdx.x & 31;
    if (w >= NN) return;
    const int hop = blockIdx.y;
    const int*   __restrict__ csr = g_csr[hop];
    const float* __restrict__ AS  = g_as[hop];
    const float* __restrict__ AD  = g_ad[hop];
    const float* bias = hop ? b1 : b0;
    const int n = w;
    const int beg = g_off[hop][n], end = g_off[hop][n + 1];
    const float self_mult = (hop == 1) ? 2.0f : 1.0f;
    const int hE = l & 7;       // head during exp phase
    const int hC = l >> 2;      // head of this lane's channel group

    float adv = 0.f, asv = 0.f;
    if (l < HH) { adv = AD[n * HH + l]; asv = AS[n * HH + l]; }
    float ad_all = __shfl_sync(0xffffffffu, adv, hE);

    float sv = (l < HH) ? self_mult * __expf(lrelu(asv + adv)) : 0.f;
    float shacc = sv;

    float pb = __shfl_sync(0xffffffffu, sv, hC);
    float4 xv = *(const float4*)(g_xw + n * 256 + hop * 128 + l * 4);
    float4 acc = make_float4(pb * xv.x, pb * xv.y, pb * xv.z, pb * xv.w);

    for (int base = beg; base < end; base += 16) {
        const int nv = end - base;
        int sl = 0;
        if (l < 16) sl = csr[base + min(l, nv - 1)];
        float wg[4];
#pragma unroll
        for (int r = 0; r < 4; r++) {
            int e = r * 4 + (l >> 3);
            int s = __shfl_sync(0xffffffffu, sl, e);
            wg[r] = 0.f;
            if (e < nv) wg[r] = __expf(lrelu(__ldg(AS + s * HH + hE) + ad_all));
            shacc += wg[r];
        }
        const int cnt = min(16, nv);
#pragma unroll
        for (int gg = 0; gg < 16; gg++) {
            if (gg < cnt) {
                float pw = __shfl_sync(0xffffffffu, wg[gg >> 2], (gg & 3) * 8 + hC);
                int s = __shfl_sync(0xffffffffu, sl, gg);
                float4 mv = __ldg((const float4*)(g_xw + s * 256 + hop * 128 + l * 4));
                acc.x += pw * mv.x;
                acc.y += pw * mv.y;
                acc.z += pw * mv.z;
                acc.w += pw * mv.w;
            }
        }
    }

    shacc += __shfl_xor_sync(0xffffffffu, shacc, 8);
    shacc += __shfl_xor_sync(0xffffffffu, shacc, 16);
    float st = __shfl_sync(0xffffffffu, shacc, hC);
    float inv = 1.0f / st;
    float4 bv = *(const float4*)(bias + l * 4);
    float4 o = make_float4(acc.x * inv + bv.x, acc.y * inv + bv.y,
                           acc.z * inv + bv.z, acc.w * inv + bv.w);
    *(float4*)(out + n * 256 + hop * 128 + l * 4) = o;
}

// ---------------------- residual + LayerNorm (in-place) -----------------------
__global__ void ln_kernel(const float* __restrict__ x, const float* __restrict__ gamma,
                          const float* __restrict__ beta, float* __restrict__ out) {
    int w = (blockIdx.x * blockDim.x + threadIdx.x) >> 5;
    int l = threadIdx.x & 31;
    if (w >= NN) return;
    const int base = w * 256 + l * 8;
    float4 h0 = *(float4*)(out + base);
    float4 h1 = *(float4*)(out + base + 4);
    float4 x0 = *(const float4*)(x + base);
    float4 x1 = *(const float4*)(x + base + 4);
    float v[8] = {h0.x + x0.x, h0.y + x0.y, h0.z + x0.z, h0.w + x0.w,
                  h1.x + x1.x, h1.y + x1.y, h1.z + x1.z, h1.w + x1.w};
    float s = 0.f;
#pragma unroll
    for (int j = 0; j < 8; j++) s += v[j];
#pragma unroll
    for (int d = 16; d; d >>= 1) s += __shfl_xor_sync(0xffffffffu, s, d);
    float mean = s * (1.0f / 256.0f);
    float q = 0.f;
#pragma unroll
    for (int j = 0; j < 8; j++) { float t = v[j] - mean; q += t * t; }
#pragma unroll
    for (int d = 16; d; d >>= 1) q += __shfl_xor_sync(0xffffffffu, q, d);
    float rstd = rsqrtf(q * (1.0f / 256.0f) + 1e-5f);
    float4 g0 = *(const float4*)(gamma + l * 8);
    float4 g1 = *(const float4*)(gamma + l * 8 + 4);
    float4 b0 = *(const float4*)(beta + l * 8);
    float4 b1 = *(const float4*)(beta + l * 8 + 4);
    float4 o0 = make_float4((v[0] - mean) * rstd * g0.x + b0.x,
                            (v[1] - mean) * rstd * g0.y + b0.y,
                            (v[2] - mean) * rstd * g0.z + b0.z,
                            (v[3] - mean) * rstd * g0.w + b0.w);
    float4 o1 = make_float4((v[4] - mean) * rstd * g1.x + b1.x,
                            (v[5] - mean) * rstd * g1.y + b1.y,
                            (v[6] - mean) * rstd * g1.z + b1.z,
                            (v[7] - mean) * rstd * g1.w + b1.w);
    *(float4*)(out + base)     = o0;
    *(float4*)(out + base + 4) = o1;
}

// ------------------------------- launcher -------------------------------------
// Slot-3 (ncu capture) = fill_kernel this round. Deps: fill needs count+scan;
// gemm independent; aggregate needs gemm(att fused)+fill.
extern "C" void kernel_launch(void* const* d_in, const int* in_sizes, int n_in,
                              void* d_out, int out_size) {
    const float* x     = (const float*)d_in[0];
    const void*  ei    = d_in[1];
    const float* W0    = (const float*)d_in[2];
    const float* as0   = (const float*)d_in[3];
    const float* ad0   = (const float*)d_in[4];
    const float* b0    = (const float*)d_in[5];
    const float* W1    = (const float*)d_in[6];
    const float* as1   = (const float*)d_in[7];
    const float* ad1   = (const float*)d_in[8];
    const float* b1    = (const float*)d_in[9];
    const float* gamma = (const float*)d_in[10];
    const float* beta  = (const float*)d_in[11];
    float* out = (float*)d_out;

    cudaFuncSetAttribute(tc_gemm_kernel, cudaFuncAttributeMaxDynamicSharedMemorySize, SM_GEMM_TOTAL);

    init_kernel<<<(NN + 255) / 256, 256>>>((const int*)ei);
    count_kernel<<<(EE + 255) / 256, 256>>>(ei);
    scan_kernel<<<2, 1024>>>();
    fill_kernel<<<(EE + 255) / 256, 256>>>(ei);                                  // profiled slot
    tc_gemm_kernel<<<dim3((NN + 127) / 128, 2), 256, SM_GEMM_TOTAL>>>(x, W0, W1,
                                                                      as0, ad0, as1, ad1);
    aggregate_kernel<<<dim3((NN * 32 + 255) / 256, 2), 256>>>(b0, b1, out);
    ln_kernel<<<(NN * 32 + 255) / 256, 256>>>(x, gamma, beta, out);
}

// round 15
// speedup vs baseline: 1.6875x; 1.0781x over previous
#include <cuda_runtime.h>
#include <cuda_bf16.h>
#include <math.h>
#include <stdint.h>

#define NN 50000
#define EE 800000
#define HH 8

// ---------------- scratch (device globals: no allocation allowed) -------------
__device__ float g_xw[NN * 256];          // [x@W0 | x@W1], row stride 256
__device__ float g_as[2][NN * HH];
__device__ float g_ad[2][NN * HH];
__device__ int   g_cnt[2][NN];            // counts, then cursors
__device__ int   g_off[2][NN + 1];        // CSR offsets (by dst)
__device__ int   g_csr[2][EE];            // src per in-edge (hop2: <=NN entries)
__device__ int   g_deg[NN];               // hop-1 indegree (multiplicity source)
__device__ float g_multf[NN];             // hop-2 per-CSR-slot multiplicity
__device__ int   g_is64;

// ---------------------------------- utils ------------------------------------
__device__ __forceinline__ float lrelu(float v) { return v >= 0.f ? v : 0.2f * v; }

__device__ __forceinline__ int edge_val(const void* ei, int idx, int is64) {
    if (is64) return (int)((const long long*)ei)[idx];
    return ((const int*)ei)[idx];
}

// fp32 -> bf16 hi + bf16(residual) lo, 4 lanes packed as 2x uint2
__device__ __forceinline__ void cvt_hi_lo4(float4 v, uint2& hi, uint2& lo) {
    float f[4] = {v.x, v.y, v.z, v.w};
    unsigned short hs[4], ls[4];
#pragma unroll
    for (int i = 0; i < 4; i++) {
        __nv_bfloat16 h = __float2bfloat16(f[i]);
        hs[i] = __bfloat16_as_ushort(h);
        float r = f[i] - __bfloat162float(h);
        ls[i] = __bfloat16_as_ushort(__float2bfloat16(r));
    }
    hi = make_uint2((uint32_t)hs[0] | ((uint32_t)hs[1] << 16), (uint32_t)hs[2] | ((uint32_t)hs[3] << 16));
    lo = make_uint2((uint32_t)ls[0] | ((uint32_t)ls[1] << 16), (uint32_t)ls[2] | ((uint32_t)ls[3] << 16));
}

// dtype probe + counter zeroing fused.
__global__ void init_kernel(const int* __restrict__ p) {
    int i = blockIdx.x * blockDim.x + threadIdx.x;
    if (i < NN) { g_cnt[0][i] = 0; g_cnt[1][i] = 0; }
    if (blockIdx.x == 0) {
        __shared__ int any_nonzero;
        if (threadIdx.x == 0) any_nonzero = 0;
        __syncthreads();
        int v = 0;
        for (int j = threadIdx.x; j < 2048; j += blockDim.x) v |= p[2 * j + 1];
        if (v) atomicOr(&any_nonzero, 1);
        __syncthreads();
        if (threadIdx.x == 0) g_is64 = (any_nonzero == 0) ? 1 : 0;
    }
}

// ------------------------------ CSR build -------------------------------------
// Hop-2 compression: hop-2 edge of e is (row[col[e]], col[col[e]]) -> depends
// only on j=col[e] in [0,NN). So the hop-2 edge multiset is {(row[j], col[j])
// x indeg(j) : j<NN}: 50K weighted entries instead of 800K.
__global__ void count_kernel(const void* __restrict__ ei) {
    int e = blockIdx.x * blockDim.x + threadIdx.x;
    if (e >= EE) return;
    const int is64 = g_is64;
    int d1 = edge_val(ei, EE + e, is64);
    if (d1 >= 0 && d1 < NN) atomicAdd(&g_cnt[0][d1], 1);
    if (e < NN) {
        int d2 = edge_val(ei, EE + e, is64);   // col[j], j=e<NN
        if (d2 >= 0 && d2 < NN) atomicAdd(&g_cnt[1][d2], 1);
    }
}

// exclusive scan per hop: warp-shuffle scan; hop 0 also snapshots indegree.
__global__ void scan_kernel() {
    __shared__ int warp_sums[32];
    __shared__ int carry_s;
    const int hop = blockIdx.x;
    const int tid = threadIdx.x;
    const int lane = tid & 31, wrp = tid >> 5;
    if (tid == 0) carry_s = 0;
    __syncthreads();
    for (int base = 0; base < NN; base += 1024) {
        int i = base + tid;
        int v = (i < NN) ? g_cnt[hop][i] : 0;
        if (i < NN) {
            g_cnt[hop][i] = 0;
            if (hop == 0) g_deg[i] = v;        // save hop-1 indegree
        }
        int s = v;
#pragma unroll
        for (int d = 1; d < 32; d <<= 1) {
            int t = __shfl_up_sync(0xffffffffu, s, d);
            if (lane >= d) s += t;
        }
        if (lane == 31) warp_sums[wrp] = s;
        __syncthreads();
        if (wrp == 0) {
            int ws = warp_sums[lane];
#pragma unroll
            for (int d = 1; d < 32; d <<= 1) {
                int t = __shfl_up_sync(0xffffffffu, ws, d);
                if (lane >= d) ws += t;
            }
            warp_sums[lane] = ws;
        }
        __syncthreads();
        int excl = (wrp ? warp_sums[wrp - 1] : 0) + (s - v);
        int cbase = carry_s;
        if (i < NN) g_off[hop][i] = cbase + excl;
        int total = warp_sums[31];
        __syncthreads();
        if (tid == 0) carry_s = cbase + total;
        __syncthreads();
    }
    if (tid == 0) g_off[hop][NN] = carry_s;
}

__global__ void fill_kernel(const void* __restrict__ ei) {
    int e = blockIdx.x * blockDim.x + threadIdx.x;
    if (e >= EE) return;
    const int is64 = g_is64;
    int s1 = edge_val(ei, e, is64);
    int d1 = edge_val(ei, EE + e, is64);
    if (s1 >= 0 && s1 < NN && d1 >= 0 && d1 < NN) {
        int p = atomicAdd(&g_cnt[0][d1], 1);
        g_csr[0][g_off[0][d1] + p] = s1;
    }
    if (e < NN) {                              // hop-2 compressed entry j=e
        int s2 = s1, d2 = d1;                  // row[j], col[j]
        if (s2 >= 0 && s2 < NN && d2 >= 0 && d2 < NN) {
            int p2 = atomicAdd(&g_cnt[1][d2], 1);
            int pos = g_off[1][d2] + p2;
            g_csr[1][pos] = s2;
            g_multf[pos] = (float)g_deg[e];    // multiplicity = indeg(j)
        }
    }
}

// --------------- tensor-core GEMM: g_xw = x @ [W0|W1], bf16 3x split ----------
// mma.sync m16n8k16 bf16. CTA: 128 rows x 128 cols (blockIdx.y picks hop).
// Epilogue computes this CTA's rows' attention logits (att fused).
#define ROWB 144
#define SMA_H 0
#define SMA_L 18432
#define SMB_H 36864
#define SMB_L 55296
#define SM_GEMM_TOTAL 73728

__device__ __forceinline__ uint32_t lds32(const char* base, int row, int col) {
    return *(const uint32_t*)(base + row * ROWB + col * 2);
}
__device__ __forceinline__ void mma16816(float* c, const uint32_t* a, const uint32_t* b) {
    asm volatile(
        "mma.sync.aligned.m16n8k16.row.col.f32.bf16.bf16.f32 "
        "{%0,%1,%2,%3}, {%4,%5,%6,%7}, {%8,%9}, {%0,%1,%2,%3};"
        : "+f"(c[0]), "+f"(c[1]), "+f"(c[2]), "+f"(c[3])
        : "r"(a[0]), "r"(a[1]), "r"(a[2]), "r"(a[3]), "r"(b[0]), "r"(b[1]));
}

__global__ void __launch_bounds__(256) tc_gemm_kernel(const float* __restrict__ X,
                                                      const float* __restrict__ W0,
                                                      const float* __restrict__ W1,
                                                      const float* __restrict__ as0,
                                                      const float* __restrict__ ad0,
                                                      const float* __restrict__ as1,
                                                      const float* __restrict__ ad1) {
    extern __shared__ char smem[];
    const int tid = threadIdx.x, lane = tid & 31, wid = tid >> 5;
    const int m0 = blockIdx.x * 128;
    const int hop = blockIdx.y;
    const float* W = hop ? W1 : W0;
    const int wm = (wid & 1) * 64;
    const int wn = (wid >> 1) * 32;

    float c[4][4][4];
#pragma unroll
    for (int a = 0; a < 4; a++)
#pragma unroll
        for (int b = 0; b < 4; b++)
#pragma unroll
            for (int d = 0; d < 4; d++) c[a][b][d] = 0.f;

    const int r0 = lane >> 2;
    const int c0 = (lane & 3) * 2;

    for (int chunk = 0; chunk < 4; chunk++) {
        const int k0 = chunk * 64;
        for (int it = tid; it < 128 * 16; it += 256) {
            int r = it >> 4, q = it & 15;
            float4 v = make_float4(0.f, 0.f, 0.f, 0.f);
            if (m0 + r < NN) v = *(const float4*)(X + (m0 + r) * 256 + k0 + q * 4);
            uint2 hi, lo;
            cvt_hi_lo4(v, hi, lo);
            *(uint2*)(smem + SMA_H + r * ROWB + q * 8) = hi;
            *(uint2*)(smem + SMA_L + r * ROWB + q * 8) = lo;
        }
        for (int it = tid; it < 128 * 16; it += 256) {
            int n = it & 127, q = it >> 7;
            int kb = k0 + q * 4;
            float4 v = make_float4(__ldg(W + (kb + 0) * 128 + n), __ldg(W + (kb + 1) * 128 + n),
                                   __ldg(W + (kb + 2) * 128 + n), __ldg(W + (kb + 3) * 128 + n));
            uint2 hi, lo;
            cvt_hi_lo4(v, hi, lo);
            *(uint2*)(smem + SMB_H + n * ROWB + q * 8) = hi;
            *(uint2*)(smem + SMB_L + n * ROWB + q * 8) = lo;
        }
        __syncthreads();

#pragma unroll
        for (int ks = 0; ks < 4; ks++) {
            const int kb = ks * 16;
            uint32_t aH[4][4], aL[4][4];
#pragma unroll
            for (int mf = 0; mf < 4; mf++) {
                int rb = wm + mf * 16;
                aH[mf][0] = lds32(smem + SMA_H, rb + r0,     kb + c0);
                aH[mf][1] = lds32(smem + SMA_H, rb + r0 + 8, kb + c0);
                aH[mf][2] = lds32(smem + SMA_H, rb + r0,     kb + c0 + 8);
                aH[mf][3] = lds32(smem + SMA_H, rb + r0 + 8, kb + c0 + 8);
                aL[mf][0] = lds32(smem + SMA_L, rb + r0,     kb + c0);
                aL[mf][1] = lds32(smem + SMA_L, rb + r0 + 8, kb + c0);
                aL[mf][2] = lds32(smem + SMA_L, rb + r0,     kb + c0 + 8);
                aL[mf][3] = lds32(smem + SMA_L, rb + r0 + 8, kb + c0 + 8);
            }
            uint32_t bH[4][2], bL[4][2];
#pragma unroll
            for (int nf = 0; nf < 4; nf++) {
                int nb = wn + nf * 8 + r0;
                bH[nf][0] = lds32(smem + SMB_H, nb, kb + c0);
                bH[nf][1] = lds32(smem + SMB_H, nb, kb + c0 + 8);
                bL[nf][0] = lds32(smem + SMB_L, nb, kb + c0);
                bL[nf][1] = lds32(smem + SMB_L, nb, kb + c0 + 8);
            }
#pragma unroll
            for (int mf = 0; mf < 4; mf++)
#pragma unroll
                for (int nf = 0; nf < 4; nf++) {
                    mma16816(c[mf][nf], aH[mf], bH[nf]);
                    mma16816(c[mf][nf], aH[mf], bL[nf]);
                    mma16816(c[mf][nf], aL[mf], bH[nf]);
                }
        }
        __syncthreads();
    }

    const int colb = hop * 128 + wn;
#pragma unroll
    for (int mf = 0; mf < 4; mf++) {
        int gr = m0 + wm + mf * 16 + r0;
#pragma unroll
        for (int nf = 0; nf < 4; nf++) {
            int gc = colb + nf * 8 + c0;
            if (gr < NN)     *(float2*)(g_xw + gr * 256 + gc)       = make_float2(c[mf][nf][0], c[mf][nf][1]);
            if (gr + 8 < NN) *(float2*)(g_xw + (gr + 8) * 256 + gc) = make_float2(c[mf][nf][2], c[mf][nf][3]);
        }
    }

    // ---- fused attention logits for this CTA's 128 rows, this hop ----
    __syncthreads();
    const float* ap = hop ? as1 : as0;
    const float* dp = hop ? ad1 : ad0;
    for (int it = tid; it < 128 * 8; it += 256) {
        int r = it >> 3, h = it & 7;
        int n = m0 + r;
        if (n < NN) {
            const float* xr = g_xw + n * 256 + hop * 128 + h * 16;
            float ps = 0.f, pd = 0.f;
#pragma unroll
            for (int cc = 0; cc < 16; cc++) {
                float v = xr[cc];
                ps += v * __ldg(ap + h * 16 + cc);
                pd += v * __ldg(dp + h * 16 + cc);
            }
            g_as[hop][n * HH + h] = ps;
            g_ad[hop][n * HH + h] = pd;
        }
    }
}

// -------------------- GAT aggregation: warp per dst node ----------------------
// 16 edges/iteration. Hop 2 entries carry multiplicity (compressed multiset);
// hop-2 self-loop counted twice (reference duplicates it).
__global__ void aggregate_kernel(const float* __restrict__ b0, const float* __restrict__ b1,
                                 float* __restrict__ out) {
    int w = (blockIdx.x * blockDim.x + threadIdx.x) >> 5;
    int l = threadIdx.x & 31;
    if (w >= NN) return;
    const int hop = blockIdx.y;
    const int*   __restrict__ csr = g_csr[hop];
    const float* __restrict__ AS  = g_as[hop];
    const float* __restrict__ AD  = g_ad[hop];
    const float* bias = hop ? b1 : b0;
    const int n = w;
    const int beg = g_off[hop][n], end = g_off[hop][n + 1];
    const float self_mult = (hop == 1) ? 2.0f : 1.0f;
    const int hE = l & 7;
    const int hC = l >> 2;

    float adv = 0.f, asv = 0.f;
    if (l < HH) { adv = AD[n * HH + l]; asv = AS[n * HH + l]; }
    float ad_all = __shfl_sync(0xffffffffu, adv, hE);

    float sv = (l < HH) ? self_mult * __expf(lrelu(asv + adv)) : 0.f;
    float shacc = sv;

    float pb = __shfl_sync(0xffffffffu, sv, hC);
    float4 xv = *(const float4*)(g_xw + n * 256 + hop * 128 + l * 4);
    float4 acc = make_float4(pb * xv.x, pb * xv.y, pb * xv.z, pb * xv.w);

    for (int base = beg; base < end; base += 16) {
        const int nv = end - base;
        int sl = 0;
        float ml = 1.f;
        if (l < 16) {
            int idx = base + min(l, nv - 1);
            sl = csr[idx];
            if (hop == 1) ml = g_multf[idx];
        }
        float wg[4];
#pragma unroll
        for (int r = 0; r < 4; r++) {
            int e = r * 4 + (l >> 3);
            int s = __shfl_sync(0xffffffffu, sl, e);
            float m = __shfl_sync(0xffffffffu, ml, e);
            wg[r] = 0.f;
            if (e < nv) wg[r] = m * __expf(lrelu(__ldg(AS + s * HH + hE) + ad_all));
            shacc += wg[r];
        }
        const int cnt = min(16, nv);
#pragma unroll
        for (int gg = 0; gg < 16; gg++) {
            if (gg < cnt) {
                float pw = __shfl_sync(0xffffffffu, wg[gg >> 2], (gg & 3) * 8 + hC);
                int s = __shfl_sync(0xffffffffu, sl, gg);
                float4 mv = __ldg((const float4*)(g_xw + s * 256 + hop * 128 + l * 4));
                acc.x += pw * mv.x;
                acc.y += pw * mv.y;
                acc.z += pw * mv.z;
                acc.w += pw * mv.w;
            }
        }
    }

    shacc += __shfl_xor_sync(0xffffffffu, shacc, 8);
    shacc += __shfl_xor_sync(0xffffffffu, shacc, 16);
    float st = __shfl_sync(0xffffffffu, shacc, hC);
    float inv = 1.0f / st;
    float4 bv = *(const float4*)(bias + l * 4);
    float4 o = make_float4(acc.x * inv + bv.x, acc.y * inv + bv.y,
                           acc.z * inv + bv.z, acc.w * inv + bv.w);
    *(float4*)(out + n * 256 + hop * 128 + l * 4) = o;
}

// ---------------------- residual + LayerNorm (in-place) -----------------------
__global__ void ln_kernel(const float* __restrict__ x, const float* __restrict__ gamma,
                          const float* __restrict__ beta, float* __restrict__ out) {
    int w = (blockIdx.x * blockDim.x + threadIdx.x) >> 5;
    int l = threadIdx.x & 31;
    if (w >= NN) return;
    const int base = w * 256 + l * 8;
    float4 h0 = *(float4*)(out + base);
    float4 h1 = *(float4*)(out + base + 4);
    float4 x0 = *(const float4*)(x + base);
    float4 x1 = *(const float4*)(x + base + 4);
    float v[8] = {h0.x + x0.x, h0.y + x0.y, h0.z + x0.z, h0.w + x0.w,
                  h1.x + x1.x, h1.y + x1.y, h1.z + x1.z, h1.w + x1.w};
    float s = 0.f;
#pragma unroll
    for (int j = 0; j < 8; j++) s += v[j];
#pragma unroll
    for (int d = 16; d; d >>= 1) s += __shfl_xor_sync(0xffffffffu, s, d);
    float mean = s * (1.0f / 256.0f);
    float q = 0.f;
#pragma unroll
    for (int j = 0; j < 8; j++) { float t = v[j] - mean; q += t * t; }
#pragma unroll
    for (int d = 16; d; d >>= 1) q += __shfl_xor_sync(0xffffffffu, q, d);
    float rstd = rsqrtf(q * (1.0f / 256.0f) + 1e-5f);
    float4 g0 = *(const float4*)(gamma + l * 8);
    float4 g1 = *(const float4*)(gamma + l * 8 + 4);
    float4 b0 = *(const float4*)(beta + l * 8);
    float4 b1 = *(const float4*)(beta + l * 8 + 4);
    float4 o0 = make_float4((v[0] - mean) * rstd * g0.x + b0.x,
                            (v[1] - mean) * rstd * g0.y + b0.y,
                            (v[2] - mean) * rstd * g0.z + b0.z,
                            (v[3] - mean) * rstd * g0.w + b0.w);
    float4 o1 = make_float4((v[4] - mean) * rstd * g1.x + b1.x,
                            (v[5] - mean) * rstd * g1.y + b1.y,
                            (v[6] - mean) * rstd * g1.z + b1.z,
                            (v[7] - mean) * rstd * g1.w + b1.w);
    *(float4*)(out + base)     = o0;
    *(float4*)(out + base + 4) = o1;
}

// ------------------------------- launcher -------------------------------------
extern "C" void kernel_launch(void* const* d_in, const int* in_sizes, int n_in,
                              void* d_out, int out_size) {
    const float* x     = (const float*)d_in[0];
    const void*  ei    = d_in[1];
    const float* W0    = (const float*)d_in[2];
    const float* as0   = (const float*)d_in[3];
    const float* ad0   = (const float*)d_in[4];
    const float* b0    = (const float*)d_in[5];
    const float* W1    = (const float*)d_in[6];
    const float* as1   = (const float*)d_in[7];
    const float* ad1   = (const float*)d_in[8];
    const float* b1    = (const float*)d_in[9];
    const float* gamma = (const float*)d_in[10];
    const float* beta  = (const float*)d_in[11];
    float* out = (float*)d_out;

    cudaFuncSetAttribute(tc_gemm_kernel, cudaFuncAttributeMaxDynamicSharedMemorySize, SM_GEMM_TOTAL);

    init_kernel<<<(NN + 255) / 256, 256>>>((const int*)ei);
    count_kernel<<<(EE + 255) / 256, 256>>>(ei);
    scan_kernel<<<2, 1024>>>();
    fill_kernel<<<(EE + 255) / 256, 256>>>(ei);                                  // profiled slot
    tc_gemm_kernel<<<dim3((NN + 127) / 128, 2), 256, SM_GEMM_TOTAL>>>(x, W0, W1,
                                                                      as0, ad0, as1, ad1);
    aggregate_kernel<<<dim3((NN * 32 + 255) / 256, 2), 256>>>(b0, b1, out);
    ln_kernel<<<(NN * 32 + 255) / 256, 256>>>(x, gamma, beta, out);
}